// round 10
// baseline (speedup 1.0000x reference)
#include <cuda_runtime.h>
#include <cuda_bf16.h>
#include <cuda_fp16.h>
#include <cstdint>

#define BATCH   4
#define SEQ     2048
#define DMODEL  1024
#define NHEADS  16
#define DK      64
#define MROWS   (BATCH * SEQ)                 // 8192
#define HEADELEMS (BATCH * NHEADS * SEQ * DK) // 8M

// ---------------- persistent scratch (all fp16 now) -------------------------
__device__ __half g_INh[3 * MROWS * DMODEL];
__device__ __half g_INl[3 * MROWS * DMODEL];
__device__ __half g_W[4 * DMODEL * DMODEL];
__device__ __half g_CtxH[MROWS * DMODEL], g_CtxL[MROWS * DMODEL];
__device__ __half g_Qh[HEADELEMS], g_Ql[HEADELEMS];
__device__ __half g_Kh[HEADELEMS], g_Kl[HEADELEMS];
__device__ __half g_Vh[HEADELEMS], g_Vl[HEADELEMS];

// ============================ helpers ======================================
__device__ __forceinline__ uint32_t smem_u32(const void* p) {
    uint32_t a;
    asm("{ .reg .u64 t; cvta.to.shared.u64 t, %1; cvt.u32.u64 %0, t; }"
        : "=r"(a) : "l"(p));
    return a;
}
#define LDSM_X4(r, addr) \
    asm volatile("ldmatrix.sync.aligned.m8n8.x4.shared.b16 {%0,%1,%2,%3}, [%4];" \
        : "=r"((r)[0]), "=r"((r)[1]), "=r"((r)[2]), "=r"((r)[3]) : "r"(addr))
#define LDSM_X4_T(r, addr) \
    asm volatile("ldmatrix.sync.aligned.m8n8.x4.trans.shared.b16 {%0,%1,%2,%3}, [%4];" \
        : "=r"((r)[0]), "=r"((r)[1]), "=r"((r)[2]), "=r"((r)[3]) : "r"(addr))
#define CP16(dst, src) \
    asm volatile("cp.async.cg.shared.global [%0], [%1], 16;" \
                 :: "r"(dst), "l"(src) : "memory")
#define CP_COMMIT() asm volatile("cp.async.commit_group;" ::: "memory")
#define CP_WAIT0()  asm volatile("cp.async.wait_group 0;" ::: "memory")
#define CP_WAIT1()  asm volatile("cp.async.wait_group 1;" ::: "memory")

// f32-accumulator fp16 HMMA
__device__ __forceinline__ void mma_f16(float* c, const uint32_t* a,
                                        uint32_t b0, uint32_t b1) {
    asm volatile("mma.sync.aligned.m16n8k16.row.col.f32.f16.f16.f32 "
        "{%0,%1,%2,%3}, {%4,%5,%6,%7}, {%8,%9}, {%0,%1,%2,%3};"
        : "+f"(c[0]), "+f"(c[1]), "+f"(c[2]), "+f"(c[3])
        : "r"(a[0]), "r"(a[1]), "r"(a[2]), "r"(a[3]), "r"(b0), "r"(b1));
}
// f16-accumulator fp16 HMMA (theory: 2x rate) — D/C are 2 f16x2 regs
__device__ __forceinline__ void mma_f16acc(uint32_t* c, const uint32_t* a,
                                           uint32_t b0, uint32_t b1) {
    asm volatile("mma.sync.aligned.m16n8k16.row.col.f16.f16.f16.f16 "
        "{%0,%1}, {%2,%3,%4,%5}, {%6,%7}, {%0,%1};"
        : "+r"(c[0]), "+r"(c[1])
        : "r"(a[0]), "r"(a[1]), "r"(a[2]), "r"(a[3]), "r"(b0), "r"(b1));
}
// merge f16x2 pair-accumulator into the 4-float f32 accumulator
__device__ __forceinline__ void merge_lo(float* c, uint32_t* l) {
    const __half2 a = *(const __half2*)&l[0];
    const __half2 b = *(const __half2*)&l[1];
    c[0] += __low2float(a);  c[1] += __high2float(a);
    c[2] += __low2float(b);  c[3] += __high2float(b);
    l[0] = 0u; l[1] = 0u;
}

__device__ __forceinline__ void split_pack2_f16(float x, float y,
                                                uint32_t& hi, uint32_t& lo) {
    __half2 h = __floats2half2_rn(x, y);
    const float rx = x - __half2float(__low2half(h));
    const float ry = y - __half2float(__high2half(h));
    __half2 l = __floats2half2_rn(rx, ry);
    hi = *reinterpret_cast<uint32_t*>(&h);
    lo = *reinterpret_cast<uint32_t*>(&l);
}

// ===========================================================================
// Pre-split pass (unchanged).
// ===========================================================================
__global__ void __launch_bounds__(256) ksplit(
    const float* __restrict__ q, const float* __restrict__ k,
    const float* __restrict__ v, const float* __restrict__ wq,
    const float* __restrict__ wk, const float* __restrict__ wv,
    const float* __restrict__ wo) {
    const int sel = blockIdx.y;
    const int i = (blockIdx.x * 256 + threadIdx.x) * 8;
    if (sel < 3) {
        const float* src = (sel == 0) ? q : (sel == 1) ? k : v;
        __half* h = g_INh + (size_t)sel * MROWS * DMODEL;
        __half* l = g_INl + (size_t)sel * MROWS * DMODEL;
        const float4 a = *(const float4*)(src + i);
        const float4 b = *(const float4*)(src + i + 4);
        uint32_t h0, l0, h1, l1, h2, l2, h3, l3;
        split_pack2_f16(a.x, a.y, h0, l0);
        split_pack2_f16(a.z, a.w, h1, l1);
        split_pack2_f16(b.x, b.y, h2, l2);
        split_pack2_f16(b.z, b.w, h3, l3);
        *(uint4*)(h + i) = make_uint4(h0, h1, h2, h3);
        *(uint4*)(l + i) = make_uint4(l0, l1, l2, l3);
    } else {
        const int w = sel - 3;
        if (i >= DMODEL * DMODEL) return;
        const float* src = (w == 0) ? wq : (w == 1) ? wk : (w == 2) ? wv : wo;
        __half* h = g_W + (size_t)w * DMODEL * DMODEL;
        const float4 a = *(const float4*)(src + i);
        const float4 b = *(const float4*)(src + i + 4);
        __half2 h0 = __floats2half2_rn(a.x, a.y);
        __half2 h1 = __floats2half2_rn(a.z, a.w);
        __half2 h2 = __floats2half2_rn(b.x, b.y);
        __half2 h3 = __floats2half2_rn(b.z, b.w);
        *(uint4*)(h + i) = make_uint4(*(uint32_t*)&h0, *(uint32_t*)&h1,
                                      *(uint32_t*)&h2, *(uint32_t*)&h3);
    }
}

// ===========================================================================
// fp16 2-product HMMA NT GEMM — hi product f32-acc, lo product f16-acc.
// 512 threads, warp tile 32x32, CTA 128x128, BK=32, 3-stage cp.async.
// ===========================================================================
#define GS_ROW   80
#define GS_TILE  10240
#define GS_STAGE (3 * GS_TILE)
#define GS_NSTG  3
#define GEMM_SMEM (GS_NSTG * GS_STAGE)   // 92160

template <int MODE>
__global__ void __launch_bounds__(512, 2) gemm_hmma(float* __restrict__ Yout) {
    extern __shared__ char smem[];
    const uint32_t sb = smem_u32(smem);
    const int tid  = threadIdx.x;
    const int wid  = tid >> 5;
    const int lane = tid & 31;
    const int m0 = blockIdx.y * 128;
    const int n0 = blockIdx.x * 128;

    const __half *Ah, *Al, *Bw;
    int z = 0;
    if (MODE == 0) {
        z  = blockIdx.z;
        Ah = g_INh + (size_t)z * MROWS * DMODEL;
        Al = g_INl + (size_t)z * MROWS * DMODEL;
        Bw = g_W + (size_t)z * DMODEL * DMODEL;
    } else {
        Ah = g_CtxH; Al = g_CtxL;
        Bw = g_W + (size_t)3 * DMODEL * DMODEL;
    }

    const int prow = tid >> 2;
    const int pc   = tid & 3;
    const __half* srcAh = Ah + (size_t)(m0 + prow) * DMODEL + pc * 8;
    const __half* srcAl = Al + (size_t)(m0 + prow) * DMODEL + pc * 8;
    const __half* srcB  = Bw + (size_t)(n0 + prow) * DMODEL + pc * 8;
    const uint32_t pdst = (uint32_t)prow * GS_ROW + pc * 16;

    auto prefetch = [&](int ks, int st) {
        const uint32_t s0 = sb + st * GS_STAGE + pdst;
        const int ko = ks * 32;
        CP16(s0 + 0 * GS_TILE, srcAh + ko);
        CP16(s0 + 1 * GS_TILE, srcAl + ko);
        CP16(s0 + 2 * GS_TILE, srcB + ko);
    };

    const int wm = (wid & 3) * 32;
    const int wn = (wid >> 2) * 32;
    const int aRow  = lane & 15;
    const int aColB = (lane >> 4) * 16;
    const int bRow  = ((lane >> 4) << 3) + (lane & 7);
    const int bColB = ((lane >> 3) & 1) * 16;
    const uint32_t aOff = (uint32_t)(wm + aRow) * GS_ROW + aColB;
    const uint32_t bOff = (uint32_t)(wn + bRow) * GS_ROW + bColB;

    float acc[2][4][4];
    uint32_t accl[2][4][2];
#pragma unroll
    for (int mt = 0; mt < 2; mt++)
#pragma unroll
        for (int nt = 0; nt < 4; nt++) {
#pragma unroll
            for (int e = 0; e < 4; e++) acc[mt][nt][e] = 0.f;
            accl[mt][nt][0] = 0u; accl[mt][nt][1] = 0u;
        }

    prefetch(0, 0); CP_COMMIT();
    prefetch(1, 1); CP_COMMIT();

    int stg = 0;
    for (int ks = 0; ks < 32; ks++) {
        CP_WAIT1();
        __syncthreads();
        if (ks + 2 < 32) {
            const int nst = (stg + 2 >= GS_NSTG) ? stg + 2 - GS_NSTG : stg + 2;
            prefetch(ks + 2, nst);
        }
        CP_COMMIT();

        const uint32_t st = sb + stg * GS_STAGE;
        const uint32_t aH = st + aOff;
        const uint32_t aL = st + GS_TILE + aOff;
        const uint32_t bB = st + 2 * GS_TILE + bOff;

#pragma unroll
        for (int k16 = 0; k16 < 2; k16++) {
            const uint32_t kb = k16 * 32;
            uint32_t AfH[2][4], AfL[2][4], Bf[2][4];
#pragma unroll
            for (int mt = 0; mt < 2; mt++) {
                LDSM_X4(AfH[mt], aH + mt * (16 * GS_ROW) + kb);
                LDSM_X4(AfL[mt], aL + mt * (16 * GS_ROW) + kb);
            }
#pragma unroll
            for (int p = 0; p < 2; p++)
                LDSM_X4(Bf[p], bB + p * (16 * GS_ROW) + kb);
#pragma unroll
            for (int mt = 0; mt < 2; mt++)
#pragma unroll
                for (int nt = 0; nt < 4; nt++) {
                    const int p = nt >> 1, q2 = (nt & 1) * 2;
                    mma_f16(acc[mt][nt], AfH[mt], Bf[p][q2], Bf[p][q2 + 1]);
                    mma_f16acc(accl[mt][nt], AfL[mt], Bf[p][q2], Bf[p][q2 + 1]);
                }
        }
        stg = (stg + 1 >= GS_NSTG) ? 0 : stg + 1;
    }

    // ---- epilogue ----
    __half *OH = nullptr, *OL = nullptr;
    if (MODE == 0) {
        OH = (z == 0) ? g_Qh : (z == 1) ? g_Kh : g_Vh;
        OL = (z == 0) ? g_Ql : (z == 1) ? g_Kl : g_Vl;
    }
    const int g  = lane >> 2;
    const int tq = lane & 3;
#pragma unroll
    for (int mt = 0; mt < 2; mt++) {
#pragma unroll
        for (int nt = 0; nt < 4; nt++) {
            merge_lo(acc[mt][nt], accl[mt][nt]);
            const int mrow = m0 + wm + mt * 16 + g;
            const int ncol = n0 + wn + nt * 8 + tq * 2;
#pragma unroll
            for (int half = 0; half < 2; half++) {
                const int m = mrow + half * 8;
                const float v0 = acc[mt][nt][half * 2 + 0];
                const float v1 = acc[mt][nt][half * 2 + 1];
                if (MODE == 1) {
                    *(float2*)&Yout[(size_t)m * DMODEL + ncol] = make_float2(v0, v1);
                } else {
                    const int b  = m >> 11;
                    const int s  = m & (SEQ - 1);
                    const int h  = ncol >> 6;
                    const int dc = ncol & 63;
                    const size_t off = ((size_t)(b * NHEADS + h) * SEQ + s) * DK + dc;
                    uint32_t hi, lo;
                    split_pack2_f16(v0, v1, hi, lo);
                    *(uint32_t*)&OH[off] = hi;
                    *(uint32_t*)&OL[off] = lo;
                }
            }
        }
    }
}

// ===========================================================================
// fp16 3-product causal flash attention — hi×hi f32-acc; hi×lo, lo×hi f16-acc.
// ===========================================================================
#define BSTR     144
#define KV_TILE  (64 * BSTR)
#define KV_STAGE (4 * KV_TILE)
#define ATTN_SMEM (2 * KV_STAGE)  // 73728

__global__ void __launch_bounds__(256) attn_hmma() {
    extern __shared__ char smem[];
    const uint32_t sb = smem_u32(smem);

    const int tid  = threadIdx.x;
    const int wid  = tid >> 5;
    const int lane = tid & 31;
    const int g    = lane >> 2;
    const int tq   = lane & 3;
    const int qb   = gridDim.x - 1 - blockIdx.x;
    const int bh   = blockIdx.y;

    const size_t hbase = (size_t)bh * SEQ * DK;

    {
        const int row = tid >> 1;
        const int c0  = (tid & 1) * 4;
        const __half* qh = g_Qh + hbase + (size_t)(qb * 128 + row) * DK + c0 * 8;
        const __half* ql = g_Ql + hbase + (size_t)(qb * 128 + row) * DK + c0 * 8;
        const uint32_t dh = sb + (uint32_t)row * BSTR + c0 * 16;
        const uint32_t dl = dh + 128 * BSTR;
#pragma unroll
        for (int c = 0; c < 4; c++) {
            CP16(dh + c * 16, qh + c * 8);
            CP16(dl + c * 16, ql + c * 8);
        }
        CP_COMMIT();
    }
    CP_WAIT0();
    __syncthreads();

    uint32_t Qh[4][4], Ql[4][4];
    {
        const uint32_t qlane = (uint32_t)(wid * 16 + (lane & 15)) * BSTR +
                               (uint32_t)(lane >> 4) * 16;
#pragma unroll
        for (int ks = 0; ks < 4; ks++) {
            LDSM_X4(Qh[ks], sb + qlane + ks * 32);
            LDSM_X4(Ql[ks], sb + 128 * BSTR + qlane + ks * 32);
        }
    }
    __syncthreads();

    const int krow = tid >> 2;
    const int kc0  = (tid & 3) * 2;
    const __half* sKh = g_Kh + hbase + (size_t)krow * DK + kc0 * 8;
    const __half* sKl = g_Kl + hbase + (size_t)krow * DK + kc0 * 8;
    const __half* sVh = g_Vh + hbase + (size_t)krow * DK + kc0 * 8;
    const __half* sVl = g_Vl + hbase + (size_t)krow * DK + kc0 * 8;
    const uint32_t kdst = (uint32_t)krow * BSTR + kc0 * 16;

    auto prefetchKV = [&](int kb, int st) {
        const uint32_t s0 = sb + st * KV_STAGE + kdst;
        const size_t ko = (size_t)kb * 64 * DK;
#pragma unroll
        for (int c = 0; c < 2; c++) {
            CP16(s0 + 0 * KV_TILE + c * 16, sKh + ko + c * 8);
            CP16(s0 + 1 * KV_TILE + c * 16, sKl + ko + c * 8);
            CP16(s0 + 2 * KV_TILE + c * 16, sVh + ko + c * 8);
            CP16(s0 + 3 * KV_TILE + c * 16, sVl + ko + c * 8);
        }
    };

    const uint32_t k_lane = (uint32_t)((((lane >> 4) & 1) * 8 + (lane & 7))) * BSTR +
                            (uint32_t)((lane >> 3) & 1) * 16;
    const uint32_t v_lane = (uint32_t)((((lane >> 3) & 1) * 8 + (lane & 7))) * BSTR +
                            (uint32_t)((lane >> 4) & 1) * 16;

    float o[8][4];
    uint32_t o16[8][2];
#pragma unroll
    for (int nt = 0; nt < 8; nt++) {
#pragma unroll
        for (int e = 0; e < 4; e++) o[nt][e] = 0.f;
        o16[nt][0] = 0u; o16[nt][1] = 0u;
    }
    float m0 = -1e30f, m1 = -1e30f, l0 = 0.f, l1 = 0.f;

    const int row0 = qb * 128 + wid * 16 + g;
    const int kb_end = 2 * qb + 1;

    prefetchKV(0, 0);
    CP_COMMIT();

    for (int kb = 0; kb <= kb_end; kb++) {
        CP_WAIT0();
        __syncthreads();
        if (kb < kb_end) {
            prefetchKV(kb + 1, (kb + 1) & 1);
            CP_COMMIT();
        }
        const uint32_t st = sb + (kb & 1) * KV_STAGE;

        // ---- S = Q K^T : hi×hi f32-acc, cross terms f16-acc ----
        float s[8][4];
        uint32_t s16[8][2];
#pragma unroll
        for (int nt = 0; nt < 8; nt++) {
#pragma unroll
            for (int e = 0; e < 4; e++) s[nt][e] = 0.f;
            s16[nt][0] = 0u; s16[nt][1] = 0u;
        }

#pragma unroll
        for (int ks = 0; ks < 4; ks++) {
#pragma unroll
            for (int np = 0; np < 4; np++) {
                const uint32_t ka = (uint32_t)(np * 16) * BSTR + ks * 32 + k_lane;
                uint32_t KBh[4], KBl[4];
                LDSM_X4(KBh, st + ka);
                LDSM_X4(KBl, st + KV_TILE + ka);
                mma_f16(s[2*np],   Qh[ks], KBh[0], KBh[1]);
                mma_f16(s[2*np+1], Qh[ks], KBh[2], KBh[3]);
                mma_f16acc(s16[2*np],   Qh[ks], KBl[0], KBl[1]);
                mma_f16acc(s16[2*np+1], Qh[ks], KBl[2], KBl[3]);
                mma_f16acc(s16[2*np],   Ql[ks], KBh[0], KBh[1]);
                mma_f16acc(s16[2*np+1], Ql[ks], KBh[2], KBh[3]);
            }
        }
#pragma unroll
        for (int nt = 0; nt < 8; nt++) merge_lo(s[nt], s16[nt]);

#pragma unroll
        for (int nt = 0; nt < 8; nt++)
#pragma unroll
            for (int e = 0; e < 4; e++) s[nt][e] *= 0.125f;

        if (kb >= 2 * qb) {
            const int cb = kb * 64 + 2 * tq;
#pragma unroll
            for (int nt = 0; nt < 8; nt++) {
                const int c = cb + nt * 8;
                if (c     > row0)     s[nt][0] = -1e9f;
                if (c + 1 > row0)     s[nt][1] = -1e9f;
                if (c     > row0 + 8) s[nt][2] = -1e9f;
                if (c + 1 > row0 + 8) s[nt][3] = -1e9f;
            }
        }

        float rm0 = -1e30f, rm1 = -1e30f;
#pragma unroll
        for (int nt = 0; nt < 8; nt++) {
            rm0 = fmaxf(rm0, fmaxf(s[nt][0], s[nt][1]));
            rm1 = fmaxf(rm1, fmaxf(s[nt][2], s[nt][3]));
        }
        rm0 = fmaxf(rm0, __shfl_xor_sync(0xffffffffu, rm0, 1));
        rm0 = fmaxf(rm0, __shfl_xor_sync(0xffffffffu, rm0, 2));
        rm1 = fmaxf(rm1, __shfl_xor_sync(0xffffffffu, rm1, 1));
        rm1 = fmaxf(rm1, __shfl_xor_sync(0xffffffffu, rm1, 2));

        const float nm0 = fmaxf(m0, rm0);
        const float nm1 = fmaxf(m1, rm1);
        const float c0 = __expf(m0 - nm0);
        const float c1 = __expf(m1 - nm1);
        m0 = nm0; m1 = nm1;

        float rs0 = 0.f, rs1 = 0.f;
#pragma unroll
        for (int nt = 0; nt < 8; nt++) {
            s[nt][0] = __expf(s[nt][0] - nm0); rs0 += s[nt][0];
            s[nt][1] = __expf(s[nt][1] - nm0); rs0 += s[nt][1];
            s[nt][2] = __expf(s[nt][2] - nm1); rs1 += s[nt][2];
            s[nt][3] = __expf(s[nt][3] - nm1); rs1 += s[nt][3];
        }
        rs0 += __shfl_xor_sync(0xffffffffu, rs0, 1);
        rs0 += __shfl_xor_sync(0xffffffffu, rs0, 2);
        rs1 += __shfl_xor_sync(0xffffffffu, rs1, 1);
        rs1 += __shfl_xor_sync(0xffffffffu, rs1, 2);
        l0 = l0 * c0 + rs0;
        l1 = l1 * c1 + rs1;

#pragma unroll
        for (int nt = 0; nt < 8; nt++) {
            o[nt][0] *= c0; o[nt][1] *= c0;
            o[nt][2] *= c1; o[nt][3] *= c1;
        }

        // ---- O += P V : hi f32-acc, cross terms f16-acc (merged per kb) ----
#pragma unroll
        for (int kt = 0; kt < 4; kt++) {
            uint32_t PAh[4], PAl[4];
            split_pack2_f16(s[2*kt][0],   s[2*kt][1],   PAh[0], PAl[0]);
            split_pack2_f16(s[2*kt][2],   s[2*kt][3],   PAh[1], PAl[1]);
            split_pack2_f16(s[2*kt+1][0], s[2*kt+1][1], PAh[2], PAl[2]);
            split_pack2_f16(s[2*kt+1][2], s[2*kt+1][3], PAh[3], PAl[3]);
#pragma unroll
            for (int dp = 0; dp < 4; dp++) {
                const uint32_t va = (uint32_t)(kt * 16) * BSTR + dp * 32 + v_lane;
                uint32_t VBh[4], VBl[4];
                LDSM_X4_T(VBh, st + 2 * KV_TILE + va);
                LDSM_X4_T(VBl, st + 3 * KV_TILE + va);
                mma_f16(o[2*dp],   PAh, VBh[0], VBh[1]);
                mma_f16(o[2*dp+1], PAh, VBh[2], VBh[3]);
                mma_f16acc(o16[2*dp],   PAh, VBl[0], VBl[1]);
                mma_f16acc(o16[2*dp+1], PAh, VBl[2], VBl[3]);
                mma_f16acc(o16[2*dp],   PAl, VBh[0], VBh[1]);
                mma_f16acc(o16[2*dp+1], PAl, VBh[2], VBh[3]);
            }
        }
#pragma unroll
        for (int nt = 0; nt < 8; nt++) merge_lo(o[nt], o16[nt]);
        __syncthreads();
    }

    // ---- normalize + fp16 split-store ctx ----
    const int b = bh >> 4;
    const int h = bh & 15;
    const float i0 = 1.f / l0;
    const float i1 = 1.f / l1;
    const size_t off0 = ((size_t)(b * SEQ + row0))     * DMODEL + h * DK + tq * 2;
    const size_t off1 = ((size_t)(b * SEQ + row0 + 8)) * DMODEL + h * DK + tq * 2;
#pragma unroll
    for (int nt = 0; nt < 8; nt++) {
        uint32_t hi, lo;
        split_pack2_f16(o[nt][0] * i0, o[nt][1] * i0, hi, lo);
        *(uint32_t*)&g_CtxH[off0 + nt * 8] = hi;
        *(uint32_t*)&g_CtxL[off0 + nt * 8] = lo;
        split_pack2_f16(o[nt][2] * i1, o[nt][3] * i1, hi, lo);
        *(uint32_t*)&g_CtxH[off1 + nt * 8] = hi;
        *(uint32_t*)&g_CtxL[off1 + nt * 8] = lo;
    }
}

// ---------------------------------------------------------------------------
extern "C" void kernel_launch(void* const* d_in, const int* in_sizes, int n_in,
                              void* d_out, int out_size) {
    const float* q  = (const float*)d_in[0];
    const float* k  = (const float*)d_in[1];
    const float* v  = (const float*)d_in[2];
    const float* wq = (const float*)d_in[3];
    const float* wk = (const float*)d_in[4];
    const float* wv = (const float*)d_in[5];
    const float* wo = (const float*)d_in[6];
    float* out = (float*)d_out;

    static int configured = 0;
    if (!configured) {
        cudaFuncSetAttribute(gemm_hmma<0>, cudaFuncAttributeMaxDynamicSharedMemorySize, GEMM_SMEM);
        cudaFuncSetAttribute(gemm_hmma<1>, cudaFuncAttributeMaxDynamicSharedMemorySize, GEMM_SMEM);
        cudaFuncSetAttribute(attn_hmma, cudaFuncAttributeMaxDynamicSharedMemorySize, ATTN_SMEM);
        configured = 1;
    }

    dim3 gs(MROWS * DMODEL / (256 * 8), 7);    // (4096, 7)
    ksplit<<<gs, 256>>>(q, k, v, wq, wk, wv, wo);

    dim3 gqkv(DMODEL / 128, MROWS / 128, 3);   // (8, 64, 3)
    gemm_hmma<0><<<gqkv, 512, GEMM_SMEM>>>(nullptr);

    dim3 ga(SEQ / 128, BATCH * NHEADS);        // (16, 64)
    attn_hmma<<<ga, 256, ATTN_SMEM>>>();

    dim3 go(DMODEL / 128, MROWS / 128);        // (8, 64)
    gemm_hmma<1><<<go, 512, GEMM_SMEM>>>(out);
}

// round 12
// speedup vs baseline: 1.6290x; 1.6290x over previous
#include <cuda_runtime.h>
#include <cuda_bf16.h>
#include <cuda_fp16.h>
#include <cstdint>

#define BATCH   4
#define SEQ     2048
#define DMODEL  1024
#define NHEADS  16
#define DK      64
#define MROWS   (BATCH * SEQ)                 // 8192
#define HEADELEMS (BATCH * NHEADS * SEQ * DK) // 8M

// ---------------- persistent scratch ---------------------------------------
__device__ __half g_INh[3 * MROWS * DMODEL];
__device__ __half g_INl[3 * MROWS * DMODEL];
__device__ __half g_W[4 * DMODEL * DMODEL];
__device__ __half g_CtxH[MROWS * DMODEL], g_CtxL[MROWS * DMODEL];
__device__ __half g_Qh[HEADELEMS], g_Ql[HEADELEMS];
__device__ __half g_Kh[HEADELEMS];          // K rounded once (no lo)
__device__ __half g_Vh[HEADELEMS];          // V rounded once (no lo)

// ============================ helpers ======================================
__device__ __forceinline__ uint32_t smem_u32(const void* p) {
    uint32_t a;
    asm("{ .reg .u64 t; cvta.to.shared.u64 t, %1; cvt.u32.u64 %0, t; }"
        : "=r"(a) : "l"(p));
    return a;
}
#define LDSM_X4(r, addr) \
    asm volatile("ldmatrix.sync.aligned.m8n8.x4.shared.b16 {%0,%1,%2,%3}, [%4];" \
        : "=r"((r)[0]), "=r"((r)[1]), "=r"((r)[2]), "=r"((r)[3]) : "r"(addr))
#define LDSM_X4_T(r, addr) \
    asm volatile("ldmatrix.sync.aligned.m8n8.x4.trans.shared.b16 {%0,%1,%2,%3}, [%4];" \
        : "=r"((r)[0]), "=r"((r)[1]), "=r"((r)[2]), "=r"((r)[3]) : "r"(addr))
#define CP16(dst, src) \
    asm volatile("cp.async.cg.shared.global [%0], [%1], 16;" \
                 :: "r"(dst), "l"(src) : "memory")
#define CP_COMMIT() asm volatile("cp.async.commit_group;" ::: "memory")
#define CP_WAIT0()  asm volatile("cp.async.wait_group 0;" ::: "memory")
#define CP_WAIT1()  asm volatile("cp.async.wait_group 1;" ::: "memory")

__device__ __forceinline__ void mma_f16(float* c, const uint32_t* a,
                                        uint32_t b0, uint32_t b1) {
    asm volatile("mma.sync.aligned.m16n8k16.row.col.f32.f16.f16.f32 "
        "{%0,%1,%2,%3}, {%4,%5,%6,%7}, {%8,%9}, {%0,%1,%2,%3};"
        : "+f"(c[0]), "+f"(c[1]), "+f"(c[2]), "+f"(c[3])
        : "r"(a[0]), "r"(a[1]), "r"(a[2]), "r"(a[3]), "r"(b0), "r"(b1));
}

__device__ __forceinline__ void split_pack2_f16(float x, float y,
                                                uint32_t& hi, uint32_t& lo) {
    __half2 h = __floats2half2_rn(x, y);
    const float rx = x - __half2float(__low2half(h));
    const float ry = y - __half2float(__high2half(h));
    __half2 l = __floats2half2_rn(rx, ry);
    hi = *reinterpret_cast<uint32_t*>(&h);
    lo = *reinterpret_cast<uint32_t*>(&l);
}

// ===========================================================================
// Pre-split pass (unchanged).
// ===========================================================================
__global__ void __launch_bounds__(256) ksplit(
    const float* __restrict__ q, const float* __restrict__ k,
    const float* __restrict__ v, const float* __restrict__ wq,
    const float* __restrict__ wk, const float* __restrict__ wv,
    const float* __restrict__ wo) {
    const int sel = blockIdx.y;
    const int i = (blockIdx.x * 256 + threadIdx.x) * 8;
    if (sel < 3) {
        const float* src = (sel == 0) ? q : (sel == 1) ? k : v;
        __half* h = g_INh + (size_t)sel * MROWS * DMODEL;
        __half* l = g_INl + (size_t)sel * MROWS * DMODEL;
        const float4 a = *(const float4*)(src + i);
        const float4 b = *(const float4*)(src + i + 4);
        uint32_t h0, l0, h1, l1, h2, l2, h3, l3;
        split_pack2_f16(a.x, a.y, h0, l0);
        split_pack2_f16(a.z, a.w, h1, l1);
        split_pack2_f16(b.x, b.y, h2, l2);
        split_pack2_f16(b.z, b.w, h3, l3);
        *(uint4*)(h + i) = make_uint4(h0, h1, h2, h3);
        *(uint4*)(l + i) = make_uint4(l0, l1, l2, l3);
    } else {
        const int w = sel - 3;
        if (i >= DMODEL * DMODEL) return;
        const float* src = (w == 0) ? wq : (w == 1) ? wk : (w == 2) ? wv : wo;
        __half* h = g_W + (size_t)w * DMODEL * DMODEL;
        const float4 a = *(const float4*)(src + i);
        const float4 b = *(const float4*)(src + i + 4);
        __half2 h0 = __floats2half2_rn(a.x, a.y);
        __half2 h1 = __floats2half2_rn(a.z, a.w);
        __half2 h2 = __floats2half2_rn(b.x, b.y);
        __half2 h3 = __floats2half2_rn(b.z, b.w);
        *(uint4*)(h + i) = make_uint4(*(uint32_t*)&h0, *(uint32_t*)&h1,
                                      *(uint32_t*)&h2, *(uint32_t*)&h3);
    }
}

// ===========================================================================
// fp16 2-product HMMA NT GEMM — round-9 form (both products f32-acc).
// 512 threads, warp tile 32x32, CTA 128x128, BK=32, 3-stage cp.async.
// Q epilogue stores hi/lo split; K/V epilogues store single rounded fp16.
// ===========================================================================
#define GS_ROW   80
#define GS_TILE  10240
#define GS_STAGE (3 * GS_TILE)
#define GS_NSTG  3
#define GEMM_SMEM (GS_NSTG * GS_STAGE)   // 92160

template <int MODE>
__global__ void __launch_bounds__(512, 2) gemm_hmma(float* __restrict__ Yout) {
    extern __shared__ char smem[];
    const uint32_t sb = smem_u32(smem);
    const int tid  = threadIdx.x;
    const int wid  = tid >> 5;
    const int lane = tid & 31;
    const int m0 = blockIdx.y * 128;
    const int n0 = blockIdx.x * 128;

    const __half *Ah, *Al, *Bw;
    int z = 0;
    if (MODE == 0) {
        z  = blockIdx.z;
        Ah = g_INh + (size_t)z * MROWS * DMODEL;
        Al = g_INl + (size_t)z * MROWS * DMODEL;
        Bw = g_W + (size_t)z * DMODEL * DMODEL;
    } else {
        Ah = g_CtxH; Al = g_CtxL;
        Bw = g_W + (size_t)3 * DMODEL * DMODEL;
    }

    const int prow = tid >> 2;
    const int pc   = tid & 3;
    const __half* srcAh = Ah + (size_t)(m0 + prow) * DMODEL + pc * 8;
    const __half* srcAl = Al + (size_t)(m0 + prow) * DMODEL + pc * 8;
    const __half* srcB  = Bw + (size_t)(n0 + prow) * DMODEL + pc * 8;
    const uint32_t pdst = (uint32_t)prow * GS_ROW + pc * 16;

    auto prefetch = [&](int ks, int st) {
        const uint32_t s0 = sb + st * GS_STAGE + pdst;
        const int ko = ks * 32;
        CP16(s0 + 0 * GS_TILE, srcAh + ko);
        CP16(s0 + 1 * GS_TILE, srcAl + ko);
        CP16(s0 + 2 * GS_TILE, srcB + ko);
    };

    const int wm = (wid & 3) * 32;
    const int wn = (wid >> 2) * 32;
    const int aRow  = lane & 15;
    const int aColB = (lane >> 4) * 16;
    const int bRow  = ((lane >> 4) << 3) + (lane & 7);
    const int bColB = ((lane >> 3) & 1) * 16;
    const uint32_t aOff = (uint32_t)(wm + aRow) * GS_ROW + aColB;
    const uint32_t bOff = (uint32_t)(wn + bRow) * GS_ROW + bColB;

    float acc[2][4][4];
#pragma unroll
    for (int mt = 0; mt < 2; mt++)
#pragma unroll
        for (int nt = 0; nt < 4; nt++)
#pragma unroll
            for (int e = 0; e < 4; e++) acc[mt][nt][e] = 0.f;

    prefetch(0, 0); CP_COMMIT();
    prefetch(1, 1); CP_COMMIT();

    int stg = 0;
    for (int ks = 0; ks < 32; ks++) {
        CP_WAIT1();
        __syncthreads();
        if (ks + 2 < 32) {
            const int nst = (stg + 2 >= GS_NSTG) ? stg + 2 - GS_NSTG : stg + 2;
            prefetch(ks + 2, nst);
        }
        CP_COMMIT();

        const uint32_t st = sb + stg * GS_STAGE;
        const uint32_t aH = st + aOff;
        const uint32_t aL = st + GS_TILE + aOff;
        const uint32_t bB = st + 2 * GS_TILE + bOff;

#pragma unroll
        for (int k16 = 0; k16 < 2; k16++) {
            const uint32_t kb = k16 * 32;
            uint32_t AfH[2][4], AfL[2][4], Bf[2][4];
#pragma unroll
            for (int mt = 0; mt < 2; mt++) {
                LDSM_X4(AfH[mt], aH + mt * (16 * GS_ROW) + kb);
                LDSM_X4(AfL[mt], aL + mt * (16 * GS_ROW) + kb);
            }
#pragma unroll
            for (int p = 0; p < 2; p++)
                LDSM_X4(Bf[p], bB + p * (16 * GS_ROW) + kb);
#pragma unroll
            for (int mt = 0; mt < 2; mt++)
#pragma unroll
                for (int nt = 0; nt < 4; nt++) {
                    const int p = nt >> 1, q2 = (nt & 1) * 2;
                    mma_f16(acc[mt][nt], AfH[mt], Bf[p][q2], Bf[p][q2 + 1]);
                    mma_f16(acc[mt][nt], AfL[mt], Bf[p][q2], Bf[p][q2 + 1]);
                }
        }
        stg = (stg + 1 >= GS_NSTG) ? 0 : stg + 1;
    }

    // ---- epilogue ----
    const int g  = lane >> 2;
    const int tq = lane & 3;
#pragma unroll
    for (int mt = 0; mt < 2; mt++) {
#pragma unroll
        for (int nt = 0; nt < 4; nt++) {
            const int mrow = m0 + wm + mt * 16 + g;
            const int ncol = n0 + wn + nt * 8 + tq * 2;
#pragma unroll
            for (int half = 0; half < 2; half++) {
                const int m = mrow + half * 8;
                const float v0 = acc[mt][nt][half * 2 + 0];
                const float v1 = acc[mt][nt][half * 2 + 1];
                if (MODE == 1) {
                    *(float2*)&Yout[(size_t)m * DMODEL + ncol] = make_float2(v0, v1);
                } else {
                    const int b  = m >> 11;
                    const int s  = m & (SEQ - 1);
                    const int h  = ncol >> 6;
                    const int dc = ncol & 63;
                    const size_t off = ((size_t)(b * NHEADS + h) * SEQ + s) * DK + dc;
                    if (z == 0) {          // Q: split hi/lo
                        uint32_t hi, lo;
                        split_pack2_f16(v0, v1, hi, lo);
                        *(uint32_t*)&g_Qh[off] = hi;
                        *(uint32_t*)&g_Ql[off] = lo;
                    } else {               // K/V: single rounding
                        __half2 hv = __floats2half2_rn(v0, v1);
                        __half* O = (z == 1) ? g_Kh : g_Vh;
                        *(uint32_t*)&O[off] = *(uint32_t*)&hv;
                    }
                }
            }
        }
    }
}

// ===========================================================================
// fp16 2-product causal flash attention: Q split / K rounded, P split / V
// rounded. All f32-acc. KV smem = Kh + Vh only.
// ===========================================================================
#define BSTR     144
#define KV_TILE  (64 * BSTR)      // 9216
#define KV_STAGE (2 * KV_TILE)    // 18432 (K, V)
#define ATTN_SMEM (2 * KV_STAGE)  // 36864 (also fits the 128x144 x2 Q staging)

__global__ void __launch_bounds__(256) attn_hmma() {
    extern __shared__ char smem[];
    const uint32_t sb = smem_u32(smem);

    const int tid  = threadIdx.x;
    const int wid  = tid >> 5;
    const int lane = tid & 31;
    const int g    = lane >> 2;
    const int tq   = lane & 3;
    const int qb   = gridDim.x - 1 - blockIdx.x;
    const int bh   = blockIdx.y;

    const size_t hbase = (size_t)bh * SEQ * DK;

    // ---- stage Q hi/lo (full-row coverage: 2 threads x 4 chunks per row) ----
    {
        const int row = tid >> 1;
        const int c0  = (tid & 1) * 4;
        const __half* qh = g_Qh + hbase + (size_t)(qb * 128 + row) * DK + c0 * 8;
        const __half* ql = g_Ql + hbase + (size_t)(qb * 128 + row) * DK + c0 * 8;
        const uint32_t dh = sb + (uint32_t)row * BSTR + c0 * 16;
        const uint32_t dl = dh + 128 * BSTR;
#pragma unroll
        for (int c = 0; c < 4; c++) {
            CP16(dh + c * 16, qh + c * 8);
            CP16(dl + c * 16, ql + c * 8);
        }
        CP_COMMIT();
    }
    CP_WAIT0();
    __syncthreads();

    uint32_t Qh[4][4], Ql[4][4];
    {
        const uint32_t qlane = (uint32_t)(wid * 16 + (lane & 15)) * BSTR +
                               (uint32_t)(lane >> 4) * 16;
#pragma unroll
        for (int ks = 0; ks < 4; ks++) {
            LDSM_X4(Qh[ks], sb + qlane + ks * 32);
            LDSM_X4(Ql[ks], sb + 128 * BSTR + qlane + ks * 32);
        }
    }
    __syncthreads();

    // KV prefetch: 64 rows x 8 chunks per row; 4 threads/row x 2 chunks each.
    const int krow = tid >> 2;
    const int kc0  = (tid & 3) * 2;               // chunk pair {0,1},{2,3},{4,5},{6,7}
    const __half* sKh = g_Kh + hbase + (size_t)krow * DK + kc0 * 8;
    const __half* sVh = g_Vh + hbase + (size_t)krow * DK + kc0 * 8;
    const uint32_t kdst = (uint32_t)krow * BSTR + kc0 * 16;

    auto prefetchKV = [&](int kb, int st) {
        const uint32_t s0 = sb + st * KV_STAGE + kdst;
        const size_t ko = (size_t)kb * 64 * DK;
        CP16(s0 + 0 * KV_TILE,      sKh + ko);
        CP16(s0 + 0 * KV_TILE + 16, sKh + ko + 8);
        CP16(s0 + 1 * KV_TILE,      sVh + ko);
        CP16(s0 + 1 * KV_TILE + 16, sVh + ko + 8);
    };

    const uint32_t k_lane = (uint32_t)((((lane >> 4) & 1) * 8 + (lane & 7))) * BSTR +
                            (uint32_t)((lane >> 3) & 1) * 16;
    const uint32_t v_lane = (uint32_t)((((lane >> 3) & 1) * 8 + (lane & 7))) * BSTR +
                            (uint32_t)((lane >> 4) & 1) * 16;

    float o[8][4];
#pragma unroll
    for (int nt = 0; nt < 8; nt++)
#pragma unroll
        for (int e = 0; e < 4; e++) o[nt][e] = 0.f;
    float m0 = -1e30f, m1 = -1e30f, l0 = 0.f, l1 = 0.f;

    const int row0 = qb * 128 + wid * 16 + g;
    const int kb_end = 2 * qb + 1;

    prefetchKV(0, 0);
    CP_COMMIT();

    for (int kb = 0; kb <= kb_end; kb++) {
        CP_WAIT0();
        __syncthreads();
        if (kb < kb_end) {
            prefetchKV(kb + 1, (kb + 1) & 1);
            CP_COMMIT();
        }
        const uint32_t st = sb + (kb & 1) * KV_STAGE;

        // ---- S = Q K^T : Qh*K + Ql*K, both f32-acc ----
        float s[8][4];
#pragma unroll
        for (int nt = 0; nt < 8; nt++)
#pragma unroll
            for (int e = 0; e < 4; e++) s[nt][e] = 0.f;

#pragma unroll
        for (int ks = 0; ks < 4; ks++) {
#pragma unroll
            for (int np = 0; np < 4; np++) {
                const uint32_t ka = (uint32_t)(np * 16) * BSTR + ks * 32 + k_lane;
                uint32_t KB[4];
                LDSM_X4(KB, st + ka);
                mma_f16(s[2*np],   Qh[ks], KB[0], KB[1]);
                mma_f16(s[2*np+1], Qh[ks], KB[2], KB[3]);
                mma_f16(s[2*np],   Ql[ks], KB[0], KB[1]);
                mma_f16(s[2*np+1], Ql[ks], KB[2], KB[3]);
            }
        }

#pragma unroll
        for (int nt = 0; nt < 8; nt++)
#pragma unroll
            for (int e = 0; e < 4; e++) s[nt][e] *= 0.125f;

        if (kb >= 2 * qb) {
            const int cb = kb * 64 + 2 * tq;
#pragma unroll
            for (int nt = 0; nt < 8; nt++) {
                const int c = cb + nt * 8;
                if (c     > row0)     s[nt][0] = -1e9f;
                if (c + 1 > row0)     s[nt][1] = -1e9f;
                if (c     > row0 + 8) s[nt][2] = -1e9f;
                if (c + 1 > row0 + 8) s[nt][3] = -1e9f;
            }
        }

        float rm0 = -1e30f, rm1 = -1e30f;
#pragma unroll
        for (int nt = 0; nt < 8; nt++) {
            rm0 = fmaxf(rm0, fmaxf(s[nt][0], s[nt][1]));
            rm1 = fmaxf(rm1, fmaxf(s[nt][2], s[nt][3]));
        }
        rm0 = fmaxf(rm0, __shfl_xor_sync(0xffffffffu, rm0, 1));
        rm0 = fmaxf(rm0, __shfl_xor_sync(0xffffffffu, rm0, 2));
        rm1 = fmaxf(rm1, __shfl_xor_sync(0xffffffffu, rm1, 1));
        rm1 = fmaxf(rm1, __shfl_xor_sync(0xffffffffu, rm1, 2));

        const float nm0 = fmaxf(m0, rm0);
        const float nm1 = fmaxf(m1, rm1);
        const float c0 = __expf(m0 - nm0);
        const float c1 = __expf(m1 - nm1);
        m0 = nm0; m1 = nm1;

        float rs0 = 0.f, rs1 = 0.f;
#pragma unroll
        for (int nt = 0; nt < 8; nt++) {
            s[nt][0] = __expf(s[nt][0] - nm0); rs0 += s[nt][0];
            s[nt][1] = __expf(s[nt][1] - nm0); rs0 += s[nt][1];
            s[nt][2] = __expf(s[nt][2] - nm1); rs1 += s[nt][2];
            s[nt][3] = __expf(s[nt][3] - nm1); rs1 += s[nt][3];
        }
        rs0 += __shfl_xor_sync(0xffffffffu, rs0, 1);
        rs0 += __shfl_xor_sync(0xffffffffu, rs0, 2);
        rs1 += __shfl_xor_sync(0xffffffffu, rs1, 1);
        rs1 += __shfl_xor_sync(0xffffffffu, rs1, 2);
        l0 = l0 * c0 + rs0;
        l1 = l1 * c1 + rs1;

#pragma unroll
        for (int nt = 0; nt < 8; nt++) {
            o[nt][0] *= c0; o[nt][1] *= c0;
            o[nt][2] *= c1; o[nt][3] *= c1;
        }

        // ---- O += P V : Ph*V + Pl*V, both f32-acc ----
#pragma unroll
        for (int kt = 0; kt < 4; kt++) {
            uint32_t PAh[4], PAl[4];
            split_pack2_f16(s[2*kt][0],   s[2*kt][1],   PAh[0], PAl[0]);
            split_pack2_f16(s[2*kt][2],   s[2*kt][3],   PAh[1], PAl[1]);
            split_pack2_f16(s[2*kt+1][0], s[2*kt+1][1], PAh[2], PAl[2]);
            split_pack2_f16(s[2*kt+1][2], s[2*kt+1][3], PAh[3], PAl[3]);
#pragma unroll
            for (int dp = 0; dp < 4; dp++) {
                const uint32_t va = (uint32_t)(kt * 16) * BSTR + dp * 32 + v_lane;
                uint32_t VB[4];
                LDSM_X4_T(VB, st + KV_TILE + va);
                mma_f16(o[2*dp],   PAh, VB[0], VB[1]);
                mma_f16(o[2*dp+1], PAh, VB[2], VB[3]);
                mma_f16(o[2*dp],   PAl, VB[0], VB[1]);
                mma_f16(o[2*dp+1], PAl, VB[2], VB[3]);
            }
        }
        __syncthreads();
    }

    // ---- normalize + fp16 split-store ctx ----
    const int b = bh >> 4;
    const int h = bh & 15;
    const float i0 = 1.f / l0;
    const float i1 = 1.f / l1;
    const size_t off0 = ((size_t)(b * SEQ + row0))     * DMODEL + h * DK + tq * 2;
    const size_t off1 = ((size_t)(b * SEQ + row0 + 8)) * DMODEL + h * DK + tq * 2;
#pragma unroll
    for (int nt = 0; nt < 8; nt++) {
        uint32_t hi, lo;
        split_pack2_f16(o[nt][0] * i0, o[nt][1] * i0, hi, lo);
        *(uint32_t*)&g_CtxH[off0 + nt * 8] = hi;
        *(uint32_t*)&g_CtxL[off0 + nt * 8] = lo;
        split_pack2_f16(o[nt][2] * i1, o[nt][3] * i1, hi, lo);
        *(uint32_t*)&g_CtxH[off1 + nt * 8] = hi;
        *(uint32_t*)&g_CtxL[off1 + nt * 8] = lo;
    }
}

// ---------------------------------------------------------------------------
extern "C" void kernel_launch(void* const* d_in, const int* in_sizes, int n_in,
                              void* d_out, int out_size) {
    const float* q  = (const float*)d_in[0];
    const float* k  = (const float*)d_in[1];
    const float* v  = (const float*)d_in[2];
    const float* wq = (const float*)d_in[3];
    const float* wk = (const float*)d_in[4];
    const float* wv = (const float*)d_in[5];
    const float* wo = (const float*)d_in[6];
    float* out = (float*)d_out;

    static int configured = 0;
    if (!configured) {
        cudaFuncSetAttribute(gemm_hmma<0>, cudaFuncAttributeMaxDynamicSharedMemorySize, GEMM_SMEM);
        cudaFuncSetAttribute(gemm_hmma<1>, cudaFuncAttributeMaxDynamicSharedMemorySize, GEMM_SMEM);
        cudaFuncSetAttribute(attn_hmma, cudaFuncAttributeMaxDynamicSharedMemorySize, ATTN_SMEM);
        configured = 1;
    }

    dim3 gs(MROWS * DMODEL / (256 * 8), 7);    // (4096, 7)
    ksplit<<<gs, 256>>>(q, k, v, wq, wk, wv, wo);

    dim3 gqkv(DMODEL / 128, MROWS / 128, 3);   // (8, 64, 3)
    gemm_hmma<0><<<gqkv, 512, GEMM_SMEM>>>(nullptr);

    dim3 ga(SEQ / 128, BATCH * NHEADS);        // (16, 64)
    attn_hmma<<<ga, 256, ATTN_SMEM>>>();

    dim3 go(DMODEL / 128, MROWS / 128);        // (8, 64)
    gemm_hmma<1><<<go, 512, GEMM_SMEM>>>(out);
}

// round 13
// speedup vs baseline: 1.8476x; 1.1341x over previous
#include <cuda_runtime.h>
#include <cuda_bf16.h>
#include <cuda_fp16.h>
#include <cstdint>

#define BATCH   4
#define SEQ     2048
#define DMODEL  1024
#define NHEADS  16
#define DK      64
#define MROWS   (BATCH * SEQ)                 // 8192
#define HEADELEMS (BATCH * NHEADS * SEQ * DK) // 8M

// ---------------- persistent scratch ---------------------------------------
__device__ __half g_INh[3 * MROWS * DMODEL];
__device__ __half g_INl[MROWS * DMODEL];      // lo only needed for query
__device__ __half g_W[4 * DMODEL * DMODEL];
__device__ __half g_CtxH[MROWS * DMODEL], g_CtxL[MROWS * DMODEL];
__device__ __half g_Qh[HEADELEMS], g_Ql[HEADELEMS];
__device__ __half g_Kh[HEADELEMS];            // K rounded once
__device__ __half g_Vh[HEADELEMS];            // V rounded once

// ============================ helpers ======================================
__device__ __forceinline__ uint32_t smem_u32(const void* p) {
    uint32_t a;
    asm("{ .reg .u64 t; cvta.to.shared.u64 t, %1; cvt.u32.u64 %0, t; }"
        : "=r"(a) : "l"(p));
    return a;
}
#define LDSM_X4(r, addr) \
    asm volatile("ldmatrix.sync.aligned.m8n8.x4.shared.b16 {%0,%1,%2,%3}, [%4];" \
        : "=r"((r)[0]), "=r"((r)[1]), "=r"((r)[2]), "=r"((r)[3]) : "r"(addr))
#define LDSM_X4_T(r, addr) \
    asm volatile("ldmatrix.sync.aligned.m8n8.x4.trans.shared.b16 {%0,%1,%2,%3}, [%4];" \
        : "=r"((r)[0]), "=r"((r)[1]), "=r"((r)[2]), "=r"((r)[3]) : "r"(addr))
#define CP16(dst, src) \
    asm volatile("cp.async.cg.shared.global [%0], [%1], 16;" \
                 :: "r"(dst), "l"(src) : "memory")
#define CP_COMMIT() asm volatile("cp.async.commit_group;" ::: "memory")
#define CP_WAIT0()  asm volatile("cp.async.wait_group 0;" ::: "memory")
#define CP_WAIT1()  asm volatile("cp.async.wait_group 1;" ::: "memory")

__device__ __forceinline__ void mma_f16(float* c, const uint32_t* a,
                                        uint32_t b0, uint32_t b1) {
    asm volatile("mma.sync.aligned.m16n8k16.row.col.f32.f16.f16.f32 "
        "{%0,%1,%2,%3}, {%4,%5,%6,%7}, {%8,%9}, {%0,%1,%2,%3};"
        : "+f"(c[0]), "+f"(c[1]), "+f"(c[2]), "+f"(c[3])
        : "r"(a[0]), "r"(a[1]), "r"(a[2]), "r"(a[3]), "r"(b0), "r"(b1));
}

__device__ __forceinline__ void split_pack2_f16(float x, float y,
                                                uint32_t& hi, uint32_t& lo) {
    __half2 h = __floats2half2_rn(x, y);
    const float rx = x - __half2float(__low2half(h));
    const float ry = y - __half2float(__high2half(h));
    __half2 l = __floats2half2_rn(rx, ry);
    hi = *reinterpret_cast<uint32_t*>(&h);
    lo = *reinterpret_cast<uint32_t*>(&l);
}

// ===========================================================================
// Pre-split pass. y=0: query -> hi/lo. y=1,2: key/value -> hi only.
// y=3..6: weights -> fp16 single.
// ===========================================================================
__global__ void __launch_bounds__(256) ksplit(
    const float* __restrict__ q, const float* __restrict__ k,
    const float* __restrict__ v, const float* __restrict__ wq,
    const float* __restrict__ wk, const float* __restrict__ wv,
    const float* __restrict__ wo) {
    const int sel = blockIdx.y;
    const int i = (blockIdx.x * 256 + threadIdx.x) * 8;
    if (sel == 0) {
        const float4 a = *(const float4*)(q + i);
        const float4 b = *(const float4*)(q + i + 4);
        uint32_t h0, l0, h1, l1, h2, l2, h3, l3;
        split_pack2_f16(a.x, a.y, h0, l0);
        split_pack2_f16(a.z, a.w, h1, l1);
        split_pack2_f16(b.x, b.y, h2, l2);
        split_pack2_f16(b.z, b.w, h3, l3);
        *(uint4*)(g_INh + i) = make_uint4(h0, h1, h2, h3);
        *(uint4*)(g_INl + i) = make_uint4(l0, l1, l2, l3);
    } else if (sel < 3) {
        const float* src = (sel == 1) ? k : v;
        __half* h = g_INh + (size_t)sel * MROWS * DMODEL;
        const float4 a = *(const float4*)(src + i);
        const float4 b = *(const float4*)(src + i + 4);
        __half2 h0 = __floats2half2_rn(a.x, a.y);
        __half2 h1 = __floats2half2_rn(a.z, a.w);
        __half2 h2 = __floats2half2_rn(b.x, b.y);
        __half2 h3 = __floats2half2_rn(b.z, b.w);
        *(uint4*)(h + i) = make_uint4(*(uint32_t*)&h0, *(uint32_t*)&h1,
                                      *(uint32_t*)&h2, *(uint32_t*)&h3);
    } else {
        const int w = sel - 3;
        if (i >= DMODEL * DMODEL) return;
        const float* src = (w == 0) ? wq : (w == 1) ? wk : (w == 2) ? wv : wo;
        __half* h = g_W + (size_t)w * DMODEL * DMODEL;
        const float4 a = *(const float4*)(src + i);
        const float4 b = *(const float4*)(src + i + 4);
        __half2 h0 = __floats2half2_rn(a.x, a.y);
        __half2 h1 = __floats2half2_rn(a.z, a.w);
        __half2 h2 = __floats2half2_rn(b.x, b.y);
        __half2 h3 = __floats2half2_rn(b.z, b.w);
        *(uint4*)(h + i) = make_uint4(*(uint32_t*)&h0, *(uint32_t*)&h1,
                                      *(uint32_t*)&h2, *(uint32_t*)&h3);
    }
}

// ===========================================================================
// fp16 HMMA NT GEMM. MODE 0 = Q proj (2-product, split store).
// MODE 1 = out proj (2-product, float store). MODE 2 = K/V proj (1-product,
// rounded store; blockIdx.z selects K or V).
// 512 threads, warp tile 32x32, CTA 128x128, BK=32, 3-stage cp.async.
// ===========================================================================
#define GS_ROW   80
#define GS_TILE  10240
#define GS_STAGE (3 * GS_TILE)
#define GS_NSTG  3
#define GEMM_SMEM (GS_NSTG * GS_STAGE)   // 92160

template <int MODE>
__global__ void __launch_bounds__(512, 2) gemm_hmma(float* __restrict__ Yout) {
    constexpr bool TWOPROD = (MODE != 2);
    extern __shared__ char smem[];
    const uint32_t sb = smem_u32(smem);
    const int tid  = threadIdx.x;
    const int wid  = tid >> 5;
    const int lane = tid & 31;
    const int m0 = blockIdx.y * 128;
    const int n0 = blockIdx.x * 128;

    const __half *Ah, *Al = nullptr, *Bw;
    int z = 0;
    if (MODE == 0) {
        Ah = g_INh;  Al = g_INl;
        Bw = g_W;                                // Wq
    } else if (MODE == 2) {
        z  = blockIdx.z;                         // 0 -> K, 1 -> V
        Ah = g_INh + (size_t)(z + 1) * MROWS * DMODEL;
        Bw = g_W + (size_t)(z + 1) * DMODEL * DMODEL;
    } else {
        Ah = g_CtxH; Al = g_CtxL;
        Bw = g_W + (size_t)3 * DMODEL * DMODEL;  // Wo
    }

    const int prow = tid >> 2;
    const int pc   = tid & 3;
    const __half* srcAh = Ah + (size_t)(m0 + prow) * DMODEL + pc * 8;
    const __half* srcAl = TWOPROD ? Al + (size_t)(m0 + prow) * DMODEL + pc * 8 : nullptr;
    const __half* srcB  = Bw + (size_t)(n0 + prow) * DMODEL + pc * 8;
    const uint32_t pdst = (uint32_t)prow * GS_ROW + pc * 16;

    auto prefetch = [&](int ks, int st) {
        const uint32_t s0 = sb + st * GS_STAGE + pdst;
        const int ko = ks * 32;
        CP16(s0 + 0 * GS_TILE, srcAh + ko);
        if (TWOPROD) CP16(s0 + 1 * GS_TILE, srcAl + ko);
        CP16(s0 + 2 * GS_TILE, srcB + ko);
    };

    const int wm = (wid & 3) * 32;
    const int wn = (wid >> 2) * 32;
    const int aRow  = lane & 15;
    const int aColB = (lane >> 4) * 16;
    const int bRow  = ((lane >> 4) << 3) + (lane & 7);
    const int bColB = ((lane >> 3) & 1) * 16;
    const uint32_t aOff = (uint32_t)(wm + aRow) * GS_ROW + aColB;
    const uint32_t bOff = (uint32_t)(wn + bRow) * GS_ROW + bColB;

    float acc[2][4][4];
#pragma unroll
    for (int mt = 0; mt < 2; mt++)
#pragma unroll
        for (int nt = 0; nt < 4; nt++)
#pragma unroll
            for (int e = 0; e < 4; e++) acc[mt][nt][e] = 0.f;

    prefetch(0, 0); CP_COMMIT();
    prefetch(1, 1); CP_COMMIT();

    int stg = 0;
    for (int ks = 0; ks < 32; ks++) {
        CP_WAIT1();
        __syncthreads();
        if (ks + 2 < 32) {
            const int nst = (stg + 2 >= GS_NSTG) ? stg + 2 - GS_NSTG : stg + 2;
            prefetch(ks + 2, nst);
        }
        CP_COMMIT();

        const uint32_t st = sb + stg * GS_STAGE;
        const uint32_t aH = st + aOff;
        const uint32_t aL = st + GS_TILE + aOff;
        const uint32_t bB = st + 2 * GS_TILE + bOff;

#pragma unroll
        for (int k16 = 0; k16 < 2; k16++) {
            const uint32_t kb = k16 * 32;
            uint32_t AfH[2][4], AfL[2][4], Bf[2][4];
#pragma unroll
            for (int mt = 0; mt < 2; mt++) {
                LDSM_X4(AfH[mt], aH + mt * (16 * GS_ROW) + kb);
                if (TWOPROD) LDSM_X4(AfL[mt], aL + mt * (16 * GS_ROW) + kb);
            }
#pragma unroll
            for (int p = 0; p < 2; p++)
                LDSM_X4(Bf[p], bB + p * (16 * GS_ROW) + kb);
#pragma unroll
            for (int mt = 0; mt < 2; mt++)
#pragma unroll
                for (int nt = 0; nt < 4; nt++) {
                    const int p = nt >> 1, q2 = (nt & 1) * 2;
                    mma_f16(acc[mt][nt], AfH[mt], Bf[p][q2], Bf[p][q2 + 1]);
                    if (TWOPROD)
                        mma_f16(acc[mt][nt], AfL[mt], Bf[p][q2], Bf[p][q2 + 1]);
                }
        }
        stg = (stg + 1 >= GS_NSTG) ? 0 : stg + 1;
    }

    // ---- epilogue ----
    const int g  = lane >> 2;
    const int tq = lane & 3;
#pragma unroll
    for (int mt = 0; mt < 2; mt++) {
#pragma unroll
        for (int nt = 0; nt < 4; nt++) {
            const int mrow = m0 + wm + mt * 16 + g;
            const int ncol = n0 + wn + nt * 8 + tq * 2;
#pragma unroll
            for (int half = 0; half < 2; half++) {
                const int m = mrow + half * 8;
                const float v0 = acc[mt][nt][half * 2 + 0];
                const float v1 = acc[mt][nt][half * 2 + 1];
                if (MODE == 1) {
                    *(float2*)&Yout[(size_t)m * DMODEL + ncol] = make_float2(v0, v1);
                } else {
                    const int b  = m >> 11;
                    const int s  = m & (SEQ - 1);
                    const int h  = ncol >> 6;
                    const int dc = ncol & 63;
                    const size_t off = ((size_t)(b * NHEADS + h) * SEQ + s) * DK + dc;
                    if (MODE == 0) {        // Q: split hi/lo
                        uint32_t hi, lo;
                        split_pack2_f16(v0, v1, hi, lo);
                        *(uint32_t*)&g_Qh[off] = hi;
                        *(uint32_t*)&g_Ql[off] = lo;
                    } else {                // K/V: single rounding
                        __half2 hv = __floats2half2_rn(v0, v1);
                        __half* O = (z == 0) ? g_Kh : g_Vh;
                        *(uint32_t*)&O[off] = *(uint32_t*)&hv;
                    }
                }
            }
        }
    }
}

// ===========================================================================
// fp16 2-product causal flash attention (unchanged from round 12).
// ===========================================================================
#define BSTR     144
#define KV_TILE  (64 * BSTR)      // 9216
#define KV_STAGE (2 * KV_TILE)    // 18432
#define ATTN_SMEM (2 * KV_STAGE)  // 36864

__global__ void __launch_bounds__(256) attn_hmma() {
    extern __shared__ char smem[];
    const uint32_t sb = smem_u32(smem);

    const int tid  = threadIdx.x;
    const int wid  = tid >> 5;
    const int lane = tid & 31;
    const int g    = lane >> 2;
    const int tq   = lane & 3;
    const int qb   = gridDim.x - 1 - blockIdx.x;
    const int bh   = blockIdx.y;

    const size_t hbase = (size_t)bh * SEQ * DK;

    {
        const int row = tid >> 1;
        const int c0  = (tid & 1) * 4;
        const __half* qh = g_Qh + hbase + (size_t)(qb * 128 + row) * DK + c0 * 8;
        const __half* ql = g_Ql + hbase + (size_t)(qb * 128 + row) * DK + c0 * 8;
        const uint32_t dh = sb + (uint32_t)row * BSTR + c0 * 16;
        const uint32_t dl = dh + 128 * BSTR;
#pragma unroll
        for (int c = 0; c < 4; c++) {
            CP16(dh + c * 16, qh + c * 8);
            CP16(dl + c * 16, ql + c * 8);
        }
        CP_COMMIT();
    }
    CP_WAIT0();
    __syncthreads();

    uint32_t Qh[4][4], Ql[4][4];
    {
        const uint32_t qlane = (uint32_t)(wid * 16 + (lane & 15)) * BSTR +
                               (uint32_t)(lane >> 4) * 16;
#pragma unroll
        for (int ks = 0; ks < 4; ks++) {
            LDSM_X4(Qh[ks], sb + qlane + ks * 32);
            LDSM_X4(Ql[ks], sb + 128 * BSTR + qlane + ks * 32);
        }
    }
    __syncthreads();

    const int krow = tid >> 2;
    const int kc0  = (tid & 3) * 2;
    const __half* sKh = g_Kh + hbase + (size_t)krow * DK + kc0 * 8;
    const __half* sVh = g_Vh + hbase + (size_t)krow * DK + kc0 * 8;
    const uint32_t kdst = (uint32_t)krow * BSTR + kc0 * 16;

    auto prefetchKV = [&](int kb, int st) {
        const uint32_t s0 = sb + st * KV_STAGE + kdst;
        const size_t ko = (size_t)kb * 64 * DK;
        CP16(s0 + 0 * KV_TILE,      sKh + ko);
        CP16(s0 + 0 * KV_TILE + 16, sKh + ko + 8);
        CP16(s0 + 1 * KV_TILE,      sVh + ko);
        CP16(s0 + 1 * KV_TILE + 16, sVh + ko + 8);
    };

    const uint32_t k_lane = (uint32_t)((((lane >> 4) & 1) * 8 + (lane & 7))) * BSTR +
                            (uint32_t)((lane >> 3) & 1) * 16;
    const uint32_t v_lane = (uint32_t)((((lane >> 3) & 1) * 8 + (lane & 7))) * BSTR +
                            (uint32_t)((lane >> 4) & 1) * 16;

    float o[8][4];
#pragma unroll
    for (int nt = 0; nt < 8; nt++)
#pragma unroll
        for (int e = 0; e < 4; e++) o[nt][e] = 0.f;
    float m0 = -1e30f, m1 = -1e30f, l0 = 0.f, l1 = 0.f;

    const int row0 = qb * 128 + wid * 16 + g;
    const int kb_end = 2 * qb + 1;

    prefetchKV(0, 0);
    CP_COMMIT();

    for (int kb = 0; kb <= kb_end; kb++) {
        CP_WAIT0();
        __syncthreads();
        if (kb < kb_end) {
            prefetchKV(kb + 1, (kb + 1) & 1);
            CP_COMMIT();
        }
        const uint32_t st = sb + (kb & 1) * KV_STAGE;

        float s[8][4];
#pragma unroll
        for (int nt = 0; nt < 8; nt++)
#pragma unroll
            for (int e = 0; e < 4; e++) s[nt][e] = 0.f;

#pragma unroll
        for (int ks = 0; ks < 4; ks++) {
#pragma unroll
            for (int np = 0; np < 4; np++) {
                const uint32_t ka = (uint32_t)(np * 16) * BSTR + ks * 32 + k_lane;
                uint32_t KB[4];
                LDSM_X4(KB, st + ka);
                mma_f16(s[2*np],   Qh[ks], KB[0], KB[1]);
                mma_f16(s[2*np+1], Qh[ks], KB[2], KB[3]);
                mma_f16(s[2*np],   Ql[ks], KB[0], KB[1]);
                mma_f16(s[2*np+1], Ql[ks], KB[2], KB[3]);
            }
        }

#pragma unroll
        for (int nt = 0; nt < 8; nt++)
#pragma unroll
            for (int e = 0; e < 4; e++) s[nt][e] *= 0.125f;

        if (kb >= 2 * qb) {
            const int cb = kb * 64 + 2 * tq;
#pragma unroll
            for (int nt = 0; nt < 8; nt++) {
                const int c = cb + nt * 8;
                if (c     > row0)     s[nt][0] = -1e9f;
                if (c + 1 > row0)     s[nt][1] = -1e9f;
                if (c     > row0 + 8) s[nt][2] = -1e9f;
                if (c + 1 > row0 + 8) s[nt][3] = -1e9f;
            }
        }

        float rm0 = -1e30f, rm1 = -1e30f;
#pragma unroll
        for (int nt = 0; nt < 8; nt++) {
            rm0 = fmaxf(rm0, fmaxf(s[nt][0], s[nt][1]));
            rm1 = fmaxf(rm1, fmaxf(s[nt][2], s[nt][3]));
        }
        rm0 = fmaxf(rm0, __shfl_xor_sync(0xffffffffu, rm0, 1));
        rm0 = fmaxf(rm0, __shfl_xor_sync(0xffffffffu, rm0, 2));
        rm1 = fmaxf(rm1, __shfl_xor_sync(0xffffffffu, rm1, 1));
        rm1 = fmaxf(rm1, __shfl_xor_sync(0xffffffffu, rm1, 2));

        const float nm0 = fmaxf(m0, rm0);
        const float nm1 = fmaxf(m1, rm1);
        const float c0 = __expf(m0 - nm0);
        const float c1 = __expf(m1 - nm1);
        m0 = nm0; m1 = nm1;

        float rs0 = 0.f, rs1 = 0.f;
#pragma unroll
        for (int nt = 0; nt < 8; nt++) {
            s[nt][0] = __expf(s[nt][0] - nm0); rs0 += s[nt][0];
            s[nt][1] = __expf(s[nt][1] - nm0); rs0 += s[nt][1];
            s[nt][2] = __expf(s[nt][2] - nm1); rs1 += s[nt][2];
            s[nt][3] = __expf(s[nt][3] - nm1); rs1 += s[nt][3];
        }
        rs0 += __shfl_xor_sync(0xffffffffu, rs0, 1);
        rs0 += __shfl_xor_sync(0xffffffffu, rs0, 2);
        rs1 += __shfl_xor_sync(0xffffffffu, rs1, 1);
        rs1 += __shfl_xor_sync(0xffffffffu, rs1, 2);
        l0 = l0 * c0 + rs0;
        l1 = l1 * c1 + rs1;

#pragma unroll
        for (int nt = 0; nt < 8; nt++) {
            o[nt][0] *= c0; o[nt][1] *= c0;
            o[nt][2] *= c1; o[nt][3] *= c1;
        }

#pragma unroll
        for (int kt = 0; kt < 4; kt++) {
            uint32_t PAh[4], PAl[4];
            split_pack2_f16(s[2*kt][0],   s[2*kt][1],   PAh[0], PAl[0]);
            split_pack2_f16(s[2*kt][2],   s[2*kt][3],   PAh[1], PAl[1]);
            split_pack2_f16(s[2*kt+1][0], s[2*kt+1][1], PAh[2], PAl[2]);
            split_pack2_f16(s[2*kt+1][2], s[2*kt+1][3], PAh[3], PAl[3]);
#pragma unroll
            for (int dp = 0; dp < 4; dp++) {
                const uint32_t va = (uint32_t)(kt * 16) * BSTR + dp * 32 + v_lane;
                uint32_t VB[4];
                LDSM_X4_T(VB, st + KV_TILE + va);
                mma_f16(o[2*dp],   PAh, VB[0], VB[1]);
                mma_f16(o[2*dp+1], PAh, VB[2], VB[3]);
                mma_f16(o[2*dp],   PAl, VB[0], VB[1]);
                mma_f16(o[2*dp+1], PAl, VB[2], VB[3]);
            }
        }
        __syncthreads();
    }

    const int b = bh >> 4;
    const int h = bh & 15;
    const float i0 = 1.f / l0;
    const float i1 = 1.f / l1;
    const size_t off0 = ((size_t)(b * SEQ + row0))     * DMODEL + h * DK + tq * 2;
    const size_t off1 = ((size_t)(b * SEQ + row0 + 8)) * DMODEL + h * DK + tq * 2;
#pragma unroll
    for (int nt = 0; nt < 8; nt++) {
        uint32_t hi, lo;
        split_pack2_f16(o[nt][0] * i0, o[nt][1] * i0, hi, lo);
        *(uint32_t*)&g_CtxH[off0 + nt * 8] = hi;
        *(uint32_t*)&g_CtxL[off0 + nt * 8] = lo;
        split_pack2_f16(o[nt][2] * i1, o[nt][3] * i1, hi, lo);
        *(uint32_t*)&g_CtxH[off1 + nt * 8] = hi;
        *(uint32_t*)&g_CtxL[off1 + nt * 8] = lo;
    }
}

// ---------------------------------------------------------------------------
extern "C" void kernel_launch(void* const* d_in, const int* in_sizes, int n_in,
                              void* d_out, int out_size) {
    const float* q  = (const float*)d_in[0];
    const float* k  = (const float*)d_in[1];
    const float* v  = (const float*)d_in[2];
    const float* wq = (const float*)d_in[3];
    const float* wk = (const float*)d_in[4];
    const float* wv = (const float*)d_in[5];
    const float* wo = (const float*)d_in[6];
    float* out = (float*)d_out;

    static int configured = 0;
    if (!configured) {
        cudaFuncSetAttribute(gemm_hmma<0>, cudaFuncAttributeMaxDynamicSharedMemorySize, GEMM_SMEM);
        cudaFuncSetAttribute(gemm_hmma<1>, cudaFuncAttributeMaxDynamicSharedMemorySize, GEMM_SMEM);
        cudaFuncSetAttribute(gemm_hmma<2>, cudaFuncAttributeMaxDynamicSharedMemorySize, GEMM_SMEM);
        cudaFuncSetAttribute(attn_hmma, cudaFuncAttributeMaxDynamicSharedMemorySize, ATTN_SMEM);
        configured = 1;
    }

    dim3 gs(MROWS * DMODEL / (256 * 8), 7);    // (4096, 7)
    ksplit<<<gs, 256>>>(q, k, v, wq, wk, wv, wo);

    dim3 gq(DMODEL / 128, MROWS / 128);        // Q projection (2-product)
    gemm_hmma<0><<<gq, 512, GEMM_SMEM>>>(nullptr);

    dim3 gkv(DMODEL / 128, MROWS / 128, 2);    // K,V projections (1-product)
    gemm_hmma<2><<<gkv, 512, GEMM_SMEM>>>(nullptr);

    dim3 ga(SEQ / 128, BATCH * NHEADS);        // (16, 64)
    attn_hmma<<<ga, 256, ATTN_SMEM>>>();

    dim3 go(DMODEL / 128, MROWS / 128);        // output projection (2-product)
    gemm_hmma<1><<<go, 512, GEMM_SMEM>>>(out);
}

// round 14
// speedup vs baseline: 2.0561x; 1.1129x over previous
#include <cuda_runtime.h>
#include <cuda_bf16.h>
#include <cuda_fp16.h>
#include <cstdint>

#define BATCH   4
#define SEQ     2048
#define DMODEL  1024
#define NHEADS  16
#define DK      64
#define MROWS   (BATCH * SEQ)                 // 8192
#define HEADELEMS (BATCH * NHEADS * SEQ * DK) // 8M

// ---------------- persistent scratch ---------------------------------------
__device__ __half g_INh[3 * MROWS * DMODEL];
__device__ __half g_INl[MROWS * DMODEL];      // lo only needed for query
__device__ __half g_W[4 * DMODEL * DMODEL];
__device__ __half g_CtxH[MROWS * DMODEL], g_CtxL[MROWS * DMODEL];
__device__ __half g_Qh[HEADELEMS], g_Ql[HEADELEMS];   // pre-scaled by 1/8
__device__ __half g_Kh[HEADELEMS];            // K rounded once
__device__ __half g_Vh[HEADELEMS];            // V rounded once

// ============================ helpers ======================================
__device__ __forceinline__ uint32_t smem_u32(const void* p) {
    uint32_t a;
    asm("{ .reg .u64 t; cvta.to.shared.u64 t, %1; cvt.u32.u64 %0, t; }"
        : "=r"(a) : "l"(p));
    return a;
}
#define LDSM_X4(r, addr) \
    asm volatile("ldmatrix.sync.aligned.m8n8.x4.shared.b16 {%0,%1,%2,%3}, [%4];" \
        : "=r"((r)[0]), "=r"((r)[1]), "=r"((r)[2]), "=r"((r)[3]) : "r"(addr))
#define LDSM_X4_T(r, addr) \
    asm volatile("ldmatrix.sync.aligned.m8n8.x4.trans.shared.b16 {%0,%1,%2,%3}, [%4];" \
        : "=r"((r)[0]), "=r"((r)[1]), "=r"((r)[2]), "=r"((r)[3]) : "r"(addr))
#define CP16(dst, src) \
    asm volatile("cp.async.cg.shared.global [%0], [%1], 16;" \
                 :: "r"(dst), "l"(src) : "memory")
#define CP_COMMIT() asm volatile("cp.async.commit_group;" ::: "memory")
#define CP_WAIT0()  asm volatile("cp.async.wait_group 0;" ::: "memory")
#define CP_WAIT1()  asm volatile("cp.async.wait_group 1;" ::: "memory")

__device__ __forceinline__ void mma_f16(float* c, const uint32_t* a,
                                        uint32_t b0, uint32_t b1) {
    asm volatile("mma.sync.aligned.m16n8k16.row.col.f32.f16.f16.f32 "
        "{%0,%1,%2,%3}, {%4,%5,%6,%7}, {%8,%9}, {%0,%1,%2,%3};"
        : "+f"(c[0]), "+f"(c[1]), "+f"(c[2]), "+f"(c[3])
        : "r"(a[0]), "r"(a[1]), "r"(a[2]), "r"(a[3]), "r"(b0), "r"(b1));
}

__device__ __forceinline__ void split_pack2_f16(float x, float y,
                                                uint32_t& hi, uint32_t& lo) {
    __half2 h = __floats2half2_rn(x, y);
    const float rx = x - __half2float(__low2half(h));
    const float ry = y - __half2float(__high2half(h));
    __half2 l = __floats2half2_rn(rx, ry);
    hi = *reinterpret_cast<uint32_t*>(&h);
    lo = *reinterpret_cast<uint32_t*>(&l);
}

// ===========================================================================
// Pre-split pass. y=0: query -> hi/lo. y=1,2: key/value -> hi only.
// y=3..6: weights -> fp16 single.
// ===========================================================================
__global__ void __launch_bounds__(256) ksplit(
    const float* __restrict__ q, const float* __restrict__ k,
    const float* __restrict__ v, const float* __restrict__ wq,
    const float* __restrict__ wk, const float* __restrict__ wv,
    const float* __restrict__ wo) {
    const int sel = blockIdx.y;
    const int i = (blockIdx.x * 256 + threadIdx.x) * 8;
    if (sel == 0) {
        const float4 a = *(const float4*)(q + i);
        const float4 b = *(const float4*)(q + i + 4);
        uint32_t h0, l0, h1, l1, h2, l2, h3, l3;
        split_pack2_f16(a.x, a.y, h0, l0);
        split_pack2_f16(a.z, a.w, h1, l1);
        split_pack2_f16(b.x, b.y, h2, l2);
        split_pack2_f16(b.z, b.w, h3, l3);
        *(uint4*)(g_INh + i) = make_uint4(h0, h1, h2, h3);
        *(uint4*)(g_INl + i) = make_uint4(l0, l1, l2, l3);
    } else if (sel < 3) {
        const float* src = (sel == 1) ? k : v;
        __half* h = g_INh + (size_t)sel * MROWS * DMODEL;
        const float4 a = *(const float4*)(src + i);
        const float4 b = *(const float4*)(src + i + 4);
        __half2 h0 = __floats2half2_rn(a.x, a.y);
        __half2 h1 = __floats2half2_rn(a.z, a.w);
        __half2 h2 = __floats2half2_rn(b.x, b.y);
        __half2 h3 = __floats2half2_rn(b.z, b.w);
        *(uint4*)(h + i) = make_uint4(*(uint32_t*)&h0, *(uint32_t*)&h1,
                                      *(uint32_t*)&h2, *(uint32_t*)&h3);
    } else {
        const int w = sel - 3;
        if (i >= DMODEL * DMODEL) return;
        const float* src = (w == 0) ? wq : (w == 1) ? wk : (w == 2) ? wv : wo;
        __half* h = g_W + (size_t)w * DMODEL * DMODEL;
        const float4 a = *(const float4*)(src + i);
        const float4 b = *(const float4*)(src + i + 4);
        __half2 h0 = __floats2half2_rn(a.x, a.y);
        __half2 h1 = __floats2half2_rn(a.z, a.w);
        __half2 h2 = __floats2half2_rn(b.x, b.y);
        __half2 h3 = __floats2half2_rn(b.z, b.w);
        *(uint4*)(h + i) = make_uint4(*(uint32_t*)&h0, *(uint32_t*)&h1,
                                      *(uint32_t*)&h2, *(uint32_t*)&h3);
    }
}

// ===========================================================================
// fp16 HMMA NT GEMM. MODE 0 = Q proj (2-product, scaled split store).
// MODE 1 = out proj (2-product, float store). MODE 2 = K/V proj (1-product).
// ===========================================================================
#define GS_ROW   80
#define GS_TILE  10240
#define GS_STAGE (3 * GS_TILE)
#define GS_NSTG  3
#define GEMM_SMEM (GS_NSTG * GS_STAGE)   // 92160

template <int MODE>
__global__ void __launch_bounds__(512, 2) gemm_hmma(float* __restrict__ Yout) {
    constexpr bool TWOPROD = (MODE != 2);
    extern __shared__ char smem[];
    const uint32_t sb = smem_u32(smem);
    const int tid  = threadIdx.x;
    const int wid  = tid >> 5;
    const int lane = tid & 31;
    const int m0 = blockIdx.y * 128;
    const int n0 = blockIdx.x * 128;

    const __half *Ah, *Al = nullptr, *Bw;
    int z = 0;
    if (MODE == 0) {
        Ah = g_INh;  Al = g_INl;
        Bw = g_W;                                // Wq
    } else if (MODE == 2) {
        z  = blockIdx.z;                         // 0 -> K, 1 -> V
        Ah = g_INh + (size_t)(z + 1) * MROWS * DMODEL;
        Bw = g_W + (size_t)(z + 1) * DMODEL * DMODEL;
    } else {
        Ah = g_CtxH; Al = g_CtxL;
        Bw = g_W + (size_t)3 * DMODEL * DMODEL;  // Wo
    }

    const int prow = tid >> 2;
    const int pc   = tid & 3;
    const __half* srcAh = Ah + (size_t)(m0 + prow) * DMODEL + pc * 8;
    const __half* srcAl = TWOPROD ? Al + (size_t)(m0 + prow) * DMODEL + pc * 8 : nullptr;
    const __half* srcB  = Bw + (size_t)(n0 + prow) * DMODEL + pc * 8;
    const uint32_t pdst = (uint32_t)prow * GS_ROW + pc * 16;

    auto prefetch = [&](int ks, int st) {
        const uint32_t s0 = sb + st * GS_STAGE + pdst;
        const int ko = ks * 32;
        CP16(s0 + 0 * GS_TILE, srcAh + ko);
        if (TWOPROD) CP16(s0 + 1 * GS_TILE, srcAl + ko);
        CP16(s0 + 2 * GS_TILE, srcB + ko);
    };

    const int wm = (wid & 3) * 32;
    const int wn = (wid >> 2) * 32;
    const int aRow  = lane & 15;
    const int aColB = (lane >> 4) * 16;
    const int bRow  = ((lane >> 4) << 3) + (lane & 7);
    const int bColB = ((lane >> 3) & 1) * 16;
    const uint32_t aOff = (uint32_t)(wm + aRow) * GS_ROW + aColB;
    const uint32_t bOff = (uint32_t)(wn + bRow) * GS_ROW + bColB;

    float acc[2][4][4];
#pragma unroll
    for (int mt = 0; mt < 2; mt++)
#pragma unroll
        for (int nt = 0; nt < 4; nt++)
#pragma unroll
            for (int e = 0; e < 4; e++) acc[mt][nt][e] = 0.f;

    prefetch(0, 0); CP_COMMIT();
    prefetch(1, 1); CP_COMMIT();

    int stg = 0;
    for (int ks = 0; ks < 32; ks++) {
        CP_WAIT1();
        __syncthreads();
        if (ks + 2 < 32) {
            const int nst = (stg + 2 >= GS_NSTG) ? stg + 2 - GS_NSTG : stg + 2;
            prefetch(ks + 2, nst);
        }
        CP_COMMIT();

        const uint32_t st = sb + stg * GS_STAGE;
        const uint32_t aH = st + aOff;
        const uint32_t aL = st + GS_TILE + aOff;
        const uint32_t bB = st + 2 * GS_TILE + bOff;

#pragma unroll
        for (int k16 = 0; k16 < 2; k16++) {
            const uint32_t kb = k16 * 32;
            uint32_t AfH[2][4], AfL[2][4], Bf[2][4];
#pragma unroll
            for (int mt = 0; mt < 2; mt++) {
                LDSM_X4(AfH[mt], aH + mt * (16 * GS_ROW) + kb);
                if (TWOPROD) LDSM_X4(AfL[mt], aL + mt * (16 * GS_ROW) + kb);
            }
#pragma unroll
            for (int p = 0; p < 2; p++)
                LDSM_X4(Bf[p], bB + p * (16 * GS_ROW) + kb);
#pragma unroll
            for (int mt = 0; mt < 2; mt++)
#pragma unroll
                for (int nt = 0; nt < 4; nt++) {
                    const int p = nt >> 1, q2 = (nt & 1) * 2;
                    mma_f16(acc[mt][nt], AfH[mt], Bf[p][q2], Bf[p][q2 + 1]);
                    if (TWOPROD)
                        mma_f16(acc[mt][nt], AfL[mt], Bf[p][q2], Bf[p][q2 + 1]);
                }
        }
        stg = (stg + 1 >= GS_NSTG) ? 0 : stg + 1;
    }

    // ---- epilogue ----
    const int g  = lane >> 2;
    const int tq = lane & 3;
#pragma unroll
    for (int mt = 0; mt < 2; mt++) {
#pragma unroll
        for (int nt = 0; nt < 4; nt++) {
            const int mrow = m0 + wm + mt * 16 + g;
            const int ncol = n0 + wn + nt * 8 + tq * 2;
#pragma unroll
            for (int half = 0; half < 2; half++) {
                const int m = mrow + half * 8;
                const float v0 = acc[mt][nt][half * 2 + 0];
                const float v1 = acc[mt][nt][half * 2 + 1];
                if (MODE == 1) {
                    *(float2*)&Yout[(size_t)m * DMODEL + ncol] = make_float2(v0, v1);
                } else {
                    const int b  = m >> 11;
                    const int s  = m & (SEQ - 1);
                    const int h  = ncol >> 6;
                    const int dc = ncol & 63;
                    const size_t off = ((size_t)(b * NHEADS + h) * SEQ + s) * DK + dc;
                    if (MODE == 0) {        // Q: scale by 1/8, split hi/lo
                        uint32_t hi, lo;
                        split_pack2_f16(v0 * 0.125f, v1 * 0.125f, hi, lo);
                        *(uint32_t*)&g_Qh[off] = hi;
                        *(uint32_t*)&g_Ql[off] = lo;
                    } else {                // K/V: single rounding
                        __half2 hv = __floats2half2_rn(v0, v1);
                        __half* O = (z == 0) ? g_Kh : g_Vh;
                        *(uint32_t*)&O[off] = *(uint32_t*)&hv;
                    }
                }
            }
        }
    }
}

// ===========================================================================
// fp16 causal flash attention: S = 2-product (Q split, pre-scaled), PV =
// 1-product (P rounded once). All f32-acc. 2 CTAs/SM.
// ===========================================================================
#define BSTR     144
#define KV_TILE  (64 * BSTR)      // 9216
#define KV_STAGE (2 * KV_TILE)    // 18432
#define ATTN_SMEM (2 * KV_STAGE)  // 36864

__global__ void __launch_bounds__(256, 2) attn_hmma() {
    extern __shared__ char smem[];
    const uint32_t sb = smem_u32(smem);

    const int tid  = threadIdx.x;
    const int wid  = tid >> 5;
    const int lane = tid & 31;
    const int g    = lane >> 2;
    const int tq   = lane & 3;
    const int qb   = gridDim.x - 1 - blockIdx.x;
    const int bh   = blockIdx.y;

    const size_t hbase = (size_t)bh * SEQ * DK;

    {
        const int row = tid >> 1;
        const int c0  = (tid & 1) * 4;
        const __half* qh = g_Qh + hbase + (size_t)(qb * 128 + row) * DK + c0 * 8;
        const __half* ql = g_Ql + hbase + (size_t)(qb * 128 + row) * DK + c0 * 8;
        const uint32_t dh = sb + (uint32_t)row * BSTR + c0 * 16;
        const uint32_t dl = dh + 128 * BSTR;
#pragma unroll
        for (int c = 0; c < 4; c++) {
            CP16(dh + c * 16, qh + c * 8);
            CP16(dl + c * 16, ql + c * 8);
        }
        CP_COMMIT();
    }
    CP_WAIT0();
    __syncthreads();

    uint32_t Qh[4][4], Ql[4][4];
    {
        const uint32_t qlane = (uint32_t)(wid * 16 + (lane & 15)) * BSTR +
                               (uint32_t)(lane >> 4) * 16;
#pragma unroll
        for (int ks = 0; ks < 4; ks++) {
            LDSM_X4(Qh[ks], sb + qlane + ks * 32);
            LDSM_X4(Ql[ks], sb + 128 * BSTR + qlane + ks * 32);
        }
    }
    __syncthreads();

    const int krow = tid >> 2;
    const int kc0  = (tid & 3) * 2;
    const __half* sKh = g_Kh + hbase + (size_t)krow * DK + kc0 * 8;
    const __half* sVh = g_Vh + hbase + (size_t)krow * DK + kc0 * 8;
    const uint32_t kdst = (uint32_t)krow * BSTR + kc0 * 16;

    auto prefetchKV = [&](int kb, int st) {
        const uint32_t s0 = sb + st * KV_STAGE + kdst;
        const size_t ko = (size_t)kb * 64 * DK;
        CP16(s0 + 0 * KV_TILE,      sKh + ko);
        CP16(s0 + 0 * KV_TILE + 16, sKh + ko + 8);
        CP16(s0 + 1 * KV_TILE,      sVh + ko);
        CP16(s0 + 1 * KV_TILE + 16, sVh + ko + 8);
    };

    const uint32_t k_lane = (uint32_t)((((lane >> 4) & 1) * 8 + (lane & 7))) * BSTR +
                            (uint32_t)((lane >> 3) & 1) * 16;
    const uint32_t v_lane = (uint32_t)((((lane >> 3) & 1) * 8 + (lane & 7))) * BSTR +
                            (uint32_t)((lane >> 4) & 1) * 16;

    float o[8][4];
#pragma unroll
    for (int nt = 0; nt < 8; nt++)
#pragma unroll
        for (int e = 0; e < 4; e++) o[nt][e] = 0.f;
    float m0 = -1e30f, m1 = -1e30f, l0 = 0.f, l1 = 0.f;

    const int row0 = qb * 128 + wid * 16 + g;
    const int kb_end = 2 * qb + 1;

    prefetchKV(0, 0);
    CP_COMMIT();

    for (int kb = 0; kb <= kb_end; kb++) {
        CP_WAIT0();
        __syncthreads();
        if (kb < kb_end) {
            prefetchKV(kb + 1, (kb + 1) & 1);
            CP_COMMIT();
        }
        const uint32_t st = sb + (kb & 1) * KV_STAGE;

        // ---- S = Q K^T (Q pre-scaled by 1/8; 2-product) ----
        float s[8][4];
#pragma unroll
        for (int nt = 0; nt < 8; nt++)
#pragma unroll
            for (int e = 0; e < 4; e++) s[nt][e] = 0.f;

#pragma unroll
        for (int ks = 0; ks < 4; ks++) {
#pragma unroll
            for (int np = 0; np < 4; np++) {
                const uint32_t ka = (uint32_t)(np * 16) * BSTR + ks * 32 + k_lane;
                uint32_t KB[4];
                LDSM_X4(KB, st + ka);
                mma_f16(s[2*np],   Qh[ks], KB[0], KB[1]);
                mma_f16(s[2*np+1], Qh[ks], KB[2], KB[3]);
                mma_f16(s[2*np],   Ql[ks], KB[0], KB[1]);
                mma_f16(s[2*np+1], Ql[ks], KB[2], KB[3]);
            }
        }

        if (kb >= 2 * qb) {
            const int cb = kb * 64 + 2 * tq;
#pragma unroll
            for (int nt = 0; nt < 8; nt++) {
                const int c = cb + nt * 8;
                if (c     > row0)     s[nt][0] = -1e9f;
                if (c + 1 > row0)     s[nt][1] = -1e9f;
                if (c     > row0 + 8) s[nt][2] = -1e9f;
                if (c + 1 > row0 + 8) s[nt][3] = -1e9f;
            }
        }

        float rm0 = -1e30f, rm1 = -1e30f;
#pragma unroll
        for (int nt = 0; nt < 8; nt++) {
            rm0 = fmaxf(rm0, fmaxf(s[nt][0], s[nt][1]));
            rm1 = fmaxf(rm1, fmaxf(s[nt][2], s[nt][3]));
        }
        rm0 = fmaxf(rm0, __shfl_xor_sync(0xffffffffu, rm0, 1));
        rm0 = fmaxf(rm0, __shfl_xor_sync(0xffffffffu, rm0, 2));
        rm1 = fmaxf(rm1, __shfl_xor_sync(0xffffffffu, rm1, 1));
        rm1 = fmaxf(rm1, __shfl_xor_sync(0xffffffffu, rm1, 2));

        const float nm0 = fmaxf(m0, rm0);
        const float nm1 = fmaxf(m1, rm1);
        const float c0 = __expf(m0 - nm0);
        const float c1 = __expf(m1 - nm1);
        m0 = nm0; m1 = nm1;

        float rs0 = 0.f, rs1 = 0.f;
#pragma unroll
        for (int nt = 0; nt < 8; nt++) {
            s[nt][0] = __expf(s[nt][0] - nm0); rs0 += s[nt][0];
            s[nt][1] = __expf(s[nt][1] - nm0); rs0 += s[nt][1];
            s[nt][2] = __expf(s[nt][2] - nm1); rs1 += s[nt][2];
            s[nt][3] = __expf(s[nt][3] - nm1); rs1 += s[nt][3];
        }
        rs0 += __shfl_xor_sync(0xffffffffu, rs0, 1);
        rs0 += __shfl_xor_sync(0xffffffffu, rs0, 2);
        rs1 += __shfl_xor_sync(0xffffffffu, rs1, 1);
        rs1 += __shfl_xor_sync(0xffffffffu, rs1, 2);
        l0 = l0 * c0 + rs0;
        l1 = l1 * c1 + rs1;

#pragma unroll
        for (int nt = 0; nt < 8; nt++) {
            o[nt][0] *= c0; o[nt][1] *= c0;
            o[nt][2] *= c1; o[nt][3] *= c1;
        }

        // ---- O += P V : P rounded once (1-product) ----
#pragma unroll
        for (int kt = 0; kt < 4; kt++) {
            uint32_t PA[4];
            __half2 p0 = __floats2half2_rn(s[2*kt][0],   s[2*kt][1]);
            __half2 p1 = __floats2half2_rn(s[2*kt][2],   s[2*kt][3]);
            __half2 p2 = __floats2half2_rn(s[2*kt+1][0], s[2*kt+1][1]);
            __half2 p3 = __floats2half2_rn(s[2*kt+1][2], s[2*kt+1][3]);
            PA[0] = *(uint32_t*)&p0; PA[1] = *(uint32_t*)&p1;
            PA[2] = *(uint32_t*)&p2; PA[3] = *(uint32_t*)&p3;
#pragma unroll
            for (int dp = 0; dp < 4; dp++) {
                const uint32_t va = (uint32_t)(kt * 16) * BSTR + dp * 32 + v_lane;
                uint32_t VB[4];
                LDSM_X4_T(VB, st + KV_TILE + va);
                mma_f16(o[2*dp],   PA, VB[0], VB[1]);
                mma_f16(o[2*dp+1], PA, VB[2], VB[3]);
            }
        }
        __syncthreads();
    }

    const int b = bh >> 4;
    const int h = bh & 15;
    const float i0 = 1.f / l0;
    const float i1 = 1.f / l1;
    const size_t off0 = ((size_t)(b * SEQ + row0))     * DMODEL + h * DK + tq * 2;
    const size_t off1 = ((size_t)(b * SEQ + row0 + 8)) * DMODEL + h * DK + tq * 2;
#pragma unroll
    for (int nt = 0; nt < 8; nt++) {
        uint32_t hi, lo;
        split_pack2_f16(o[nt][0] * i0, o[nt][1] * i0, hi, lo);
        *(uint32_t*)&g_CtxH[off0 + nt * 8] = hi;
        *(uint32_t*)&g_CtxL[off0 + nt * 8] = lo;
        split_pack2_f16(o[nt][2] * i1, o[nt][3] * i1, hi, lo);
        *(uint32_t*)&g_CtxH[off1 + nt * 8] = hi;
        *(uint32_t*)&g_CtxL[off1 + nt * 8] = lo;
    }
}

// ---------------------------------------------------------------------------
extern "C" void kernel_launch(void* const* d_in, const int* in_sizes, int n_in,
                              void* d_out, int out_size) {
    const float* q  = (const float*)d_in[0];
    const float* k  = (const float*)d_in[1];
    const float* v  = (const float*)d_in[2];
    const float* wq = (const float*)d_in[3];
    const float* wk = (const float*)d_in[4];
    const float* wv = (const float*)d_in[5];
    const float* wo = (const float*)d_in[6];
    float* out = (float*)d_out;

    static int configured = 0;
    if (!configured) {
        cudaFuncSetAttribute(gemm_hmma<0>, cudaFuncAttributeMaxDynamicSharedMemorySize, GEMM_SMEM);
        cudaFuncSetAttribute(gemm_hmma<1>, cudaFuncAttributeMaxDynamicSharedMemorySize, GEMM_SMEM);
        cudaFuncSetAttribute(gemm_hmma<2>, cudaFuncAttributeMaxDynamicSharedMemorySize, GEMM_SMEM);
        cudaFuncSetAttribute(attn_hmma, cudaFuncAttributeMaxDynamicSharedMemorySize, ATTN_SMEM);
        configured = 1;
    }

    dim3 gs(MROWS * DMODEL / (256 * 8), 7);    // (4096, 7)
    ksplit<<<gs, 256>>>(q, k, v, wq, wk, wv, wo);

    dim3 gq(DMODEL / 128, MROWS / 128);        // Q projection (2-product)
    gemm_hmma<0><<<gq, 512, GEMM_SMEM>>>(nullptr);

    dim3 gkv(DMODEL / 128, MROWS / 128, 2);    // K,V projections (1-product)
    gemm_hmma<2><<<gkv, 512, GEMM_SMEM>>>(nullptr);

    dim3 ga(SEQ / 128, BATCH * NHEADS);        // (16, 64)
    attn_hmma<<<ga, 256, ATTN_SMEM>>>();

    dim3 go(DMODEL / 128, MROWS / 128);        // output projection (2-product)
    gemm_hmma<1><<<go, 512, GEMM_SMEM>>>(out);
}

// round 15
// speedup vs baseline: 2.2866x; 1.1121x over previous
#include <cuda_runtime.h>
#include <cuda_bf16.h>
#include <cuda_fp16.h>
#include <cstdint>

#define BATCH   4
#define SEQ     2048
#define DMODEL  1024
#define NHEADS  16
#define DK      64
#define MROWS   (BATCH * SEQ)                 // 8192
#define HEADELEMS (BATCH * NHEADS * SEQ * DK) // 8M

// ---------------- persistent scratch ---------------------------------------
__device__ __half g_INh[3 * MROWS * DMODEL];
__device__ __half g_INl[MROWS * DMODEL];      // lo only needed for query
__device__ __half g_W[4 * DMODEL * DMODEL];
__device__ __half g_CtxH[MROWS * DMODEL];     // ctx rounded once
__device__ __half g_Qh[HEADELEMS], g_Ql[HEADELEMS];   // pre-scaled by 1/8
__device__ __half g_Kh[HEADELEMS];            // K rounded once
__device__ __half g_Vh[HEADELEMS];            // V rounded once

// ============================ helpers ======================================
__device__ __forceinline__ uint32_t smem_u32(const void* p) {
    uint32_t a;
    asm("{ .reg .u64 t; cvta.to.shared.u64 t, %1; cvt.u32.u64 %0, t; }"
        : "=r"(a) : "l"(p));
    return a;
}
#define LDSM_X4(r, addr) \
    asm volatile("ldmatrix.sync.aligned.m8n8.x4.shared.b16 {%0,%1,%2,%3}, [%4];" \
        : "=r"((r)[0]), "=r"((r)[1]), "=r"((r)[2]), "=r"((r)[3]) : "r"(addr))
#define LDSM_X4_T(r, addr) \
    asm volatile("ldmatrix.sync.aligned.m8n8.x4.trans.shared.b16 {%0,%1,%2,%3}, [%4];" \
        : "=r"((r)[0]), "=r"((r)[1]), "=r"((r)[2]), "=r"((r)[3]) : "r"(addr))
#define CP16(dst, src) \
    asm volatile("cp.async.cg.shared.global [%0], [%1], 16;" \
                 :: "r"(dst), "l"(src) : "memory")
#define CP_COMMIT() asm volatile("cp.async.commit_group;" ::: "memory")
#define CP_WAIT0()  asm volatile("cp.async.wait_group 0;" ::: "memory")
#define CP_WAIT1()  asm volatile("cp.async.wait_group 1;" ::: "memory")

__device__ __forceinline__ void mma_f16(float* c, const uint32_t* a,
                                        uint32_t b0, uint32_t b1) {
    asm volatile("mma.sync.aligned.m16n8k16.row.col.f32.f16.f16.f32 "
        "{%0,%1,%2,%3}, {%4,%5,%6,%7}, {%8,%9}, {%0,%1,%2,%3};"
        : "+f"(c[0]), "+f"(c[1]), "+f"(c[2]), "+f"(c[3])
        : "r"(a[0]), "r"(a[1]), "r"(a[2]), "r"(a[3]), "r"(b0), "r"(b1));
}

__device__ __forceinline__ void split_pack2_f16(float x, float y,
                                                uint32_t& hi, uint32_t& lo) {
    __half2 h = __floats2half2_rn(x, y);
    const float rx = x - __half2float(__low2half(h));
    const float ry = y - __half2float(__high2half(h));
    __half2 l = __floats2half2_rn(rx, ry);
    hi = *reinterpret_cast<uint32_t*>(&h);
    lo = *reinterpret_cast<uint32_t*>(&l);
}

// ===========================================================================
// Pre-split pass. y=0: query -> hi/lo. y=1,2: key/value -> hi only.
// y=3..6: weights -> fp16 single.
// ===========================================================================
__global__ void __launch_bounds__(256) ksplit(
    const float* __restrict__ q, const float* __restrict__ k,
    const float* __restrict__ v, const float* __restrict__ wq,
    const float* __restrict__ wk, const float* __restrict__ wv,
    const float* __restrict__ wo) {
    const int sel = blockIdx.y;
    const int i = (blockIdx.x * 256 + threadIdx.x) * 8;
    if (sel == 0) {
        const float4 a = *(const float4*)(q + i);
        const float4 b = *(const float4*)(q + i + 4);
        uint32_t h0, l0, h1, l1, h2, l2, h3, l3;
        split_pack2_f16(a.x, a.y, h0, l0);
        split_pack2_f16(a.z, a.w, h1, l1);
        split_pack2_f16(b.x, b.y, h2, l2);
        split_pack2_f16(b.z, b.w, h3, l3);
        *(uint4*)(g_INh + i) = make_uint4(h0, h1, h2, h3);
        *(uint4*)(g_INl + i) = make_uint4(l0, l1, l2, l3);
    } else if (sel < 3) {
        const float* src = (sel == 1) ? k : v;
        __half* h = g_INh + (size_t)sel * MROWS * DMODEL;
        const float4 a = *(const float4*)(src + i);
        const float4 b = *(const float4*)(src + i + 4);
        __half2 h0 = __floats2half2_rn(a.x, a.y);
        __half2 h1 = __floats2half2_rn(a.z, a.w);
        __half2 h2 = __floats2half2_rn(b.x, b.y);
        __half2 h3 = __floats2half2_rn(b.z, b.w);
        *(uint4*)(h + i) = make_uint4(*(uint32_t*)&h0, *(uint32_t*)&h1,
                                      *(uint32_t*)&h2, *(uint32_t*)&h3);
    } else {
        const int w = sel - 3;
        if (i >= DMODEL * DMODEL) return;
        const float* src = (w == 0) ? wq : (w == 1) ? wk : (w == 2) ? wv : wo;
        __half* h = g_W + (size_t)w * DMODEL * DMODEL;
        const float4 a = *(const float4*)(src + i);
        const float4 b = *(const float4*)(src + i + 4);
        __half2 h0 = __floats2half2_rn(a.x, a.y);
        __half2 h1 = __floats2half2_rn(a.z, a.w);
        __half2 h2 = __floats2half2_rn(b.x, b.y);
        __half2 h3 = __floats2half2_rn(b.z, b.w);
        *(uint4*)(h + i) = make_uint4(*(uint32_t*)&h0, *(uint32_t*)&h1,
                                      *(uint32_t*)&h2, *(uint32_t*)&h3);
    }
}

// ===========================================================================
// fp16 HMMA NT GEMM. MODE 0 = Q proj (2-product, scaled split store).
// MODE 1 = out proj (1-product, float store). MODE 2 = K/V proj (1-product).
// ===========================================================================
#define GS_ROW   80
#define GS_TILE  10240
#define GS_STAGE (3 * GS_TILE)
#define GS_NSTG  3
#define GEMM_SMEM (GS_NSTG * GS_STAGE)   // 92160

template <int MODE>
__global__ void __launch_bounds__(512, 2) gemm_hmma(float* __restrict__ Yout) {
    constexpr bool TWOPROD = (MODE == 0);
    extern __shared__ char smem[];
    const uint32_t sb = smem_u32(smem);
    const int tid  = threadIdx.x;
    const int wid  = tid >> 5;
    const int lane = tid & 31;
    const int m0 = blockIdx.y * 128;
    const int n0 = blockIdx.x * 128;

    const __half *Ah, *Al = nullptr, *Bw;
    int z = 0;
    if (MODE == 0) {
        Ah = g_INh;  Al = g_INl;
        Bw = g_W;                                // Wq
    } else if (MODE == 2) {
        z  = blockIdx.z;                         // 0 -> K, 1 -> V
        Ah = g_INh + (size_t)(z + 1) * MROWS * DMODEL;
        Bw = g_W + (size_t)(z + 1) * DMODEL * DMODEL;
    } else {
        Ah = g_CtxH;
        Bw = g_W + (size_t)3 * DMODEL * DMODEL;  // Wo
    }

    const int prow = tid >> 2;
    const int pc   = tid & 3;
    const __half* srcAh = Ah + (size_t)(m0 + prow) * DMODEL + pc * 8;
    const __half* srcAl = TWOPROD ? Al + (size_t)(m0 + prow) * DMODEL + pc * 8 : nullptr;
    const __half* srcB  = Bw + (size_t)(n0 + prow) * DMODEL + pc * 8;
    const uint32_t pdst = (uint32_t)prow * GS_ROW + pc * 16;

    auto prefetch = [&](int ks, int st) {
        const uint32_t s0 = sb + st * GS_STAGE + pdst;
        const int ko = ks * 32;
        CP16(s0 + 0 * GS_TILE, srcAh + ko);
        if (TWOPROD) CP16(s0 + 1 * GS_TILE, srcAl + ko);
        CP16(s0 + 2 * GS_TILE, srcB + ko);
    };

    const int wm = (wid & 3) * 32;
    const int wn = (wid >> 2) * 32;
    const int aRow  = lane & 15;
    const int aColB = (lane >> 4) * 16;
    const int bRow  = ((lane >> 4) << 3) + (lane & 7);
    const int bColB = ((lane >> 3) & 1) * 16;
    const uint32_t aOff = (uint32_t)(wm + aRow) * GS_ROW + aColB;
    const uint32_t bOff = (uint32_t)(wn + bRow) * GS_ROW + bColB;

    float acc[2][4][4];
#pragma unroll
    for (int mt = 0; mt < 2; mt++)
#pragma unroll
        for (int nt = 0; nt < 4; nt++)
#pragma unroll
            for (int e = 0; e < 4; e++) acc[mt][nt][e] = 0.f;

    prefetch(0, 0); CP_COMMIT();
    prefetch(1, 1); CP_COMMIT();

    int stg = 0;
    for (int ks = 0; ks < 32; ks++) {
        CP_WAIT1();
        __syncthreads();
        if (ks + 2 < 32) {
            const int nst = (stg + 2 >= GS_NSTG) ? stg + 2 - GS_NSTG : stg + 2;
            prefetch(ks + 2, nst);
        }
        CP_COMMIT();

        const uint32_t st = sb + stg * GS_STAGE;
        const uint32_t aH = st + aOff;
        const uint32_t aL = st + GS_TILE + aOff;
        const uint32_t bB = st + 2 * GS_TILE + bOff;

#pragma unroll
        for (int k16 = 0; k16 < 2; k16++) {
            const uint32_t kb = k16 * 32;
            uint32_t AfH[2][4], AfL[2][4], Bf[2][4];
#pragma unroll
            for (int mt = 0; mt < 2; mt++) {
                LDSM_X4(AfH[mt], aH + mt * (16 * GS_ROW) + kb);
                if (TWOPROD) LDSM_X4(AfL[mt], aL + mt * (16 * GS_ROW) + kb);
            }
#pragma unroll
            for (int p = 0; p < 2; p++)
                LDSM_X4(Bf[p], bB + p * (16 * GS_ROW) + kb);
#pragma unroll
            for (int mt = 0; mt < 2; mt++)
#pragma unroll
                for (int nt = 0; nt < 4; nt++) {
                    const int p = nt >> 1, q2 = (nt & 1) * 2;
                    mma_f16(acc[mt][nt], AfH[mt], Bf[p][q2], Bf[p][q2 + 1]);
                    if (TWOPROD)
                        mma_f16(acc[mt][nt], AfL[mt], Bf[p][q2], Bf[p][q2 + 1]);
                }
        }
        stg = (stg + 1 >= GS_NSTG) ? 0 : stg + 1;
    }

    // ---- epilogue ----
    const int g  = lane >> 2;
    const int tq = lane & 3;
#pragma unroll
    for (int mt = 0; mt < 2; mt++) {
#pragma unroll
        for (int nt = 0; nt < 4; nt++) {
            const int mrow = m0 + wm + mt * 16 + g;
            const int ncol = n0 + wn + nt * 8 + tq * 2;
#pragma unroll
            for (int half = 0; half < 2; half++) {
                const int m = mrow + half * 8;
                const float v0 = acc[mt][nt][half * 2 + 0];
                const float v1 = acc[mt][nt][half * 2 + 1];
                if (MODE == 1) {
                    *(float2*)&Yout[(size_t)m * DMODEL + ncol] = make_float2(v0, v1);
                } else {
                    const int b  = m >> 11;
                    const int s  = m & (SEQ - 1);
                    const int h  = ncol >> 6;
                    const int dc = ncol & 63;
                    const size_t off = ((size_t)(b * NHEADS + h) * SEQ + s) * DK + dc;
                    if (MODE == 0) {        // Q: scale by 1/8, split hi/lo
                        uint32_t hi, lo;
                        split_pack2_f16(v0 * 0.125f, v1 * 0.125f, hi, lo);
                        *(uint32_t*)&g_Qh[off] = hi;
                        *(uint32_t*)&g_Ql[off] = lo;
                    } else {                // K/V: single rounding
                        __half2 hv = __floats2half2_rn(v0, v1);
                        __half* O = (z == 0) ? g_Kh : g_Vh;
                        *(uint32_t*)&O[off] = *(uint32_t*)&hv;
                    }
                }
            }
        }
    }
}

// ===========================================================================
// fp16 causal flash attention: S = 2-product (Q split, pre-scaled), PV =
// 1-product (P rounded once). All f32-acc. 2 CTAs/SM. Ctx stored rounded once.
// ===========================================================================
#define BSTR     144
#define KV_TILE  (64 * BSTR)      // 9216
#define KV_STAGE (2 * KV_TILE)    // 18432
#define ATTN_SMEM (2 * KV_STAGE)  // 36864

__global__ void __launch_bounds__(256, 2) attn_hmma() {
    extern __shared__ char smem[];
    const uint32_t sb = smem_u32(smem);

    const int tid  = threadIdx.x;
    const int wid  = tid >> 5;
    const int lane = tid & 31;
    const int g    = lane >> 2;
    const int tq   = lane & 3;
    const int qb   = gridDim.x - 1 - blockIdx.x;
    const int bh   = blockIdx.y;

    const size_t hbase = (size_t)bh * SEQ * DK;

    {
        const int row = tid >> 1;
        const int c0  = (tid & 1) * 4;
        const __half* qh = g_Qh + hbase + (size_t)(qb * 128 + row) * DK + c0 * 8;
        const __half* ql = g_Ql + hbase + (size_t)(qb * 128 + row) * DK + c0 * 8;
        const uint32_t dh = sb + (uint32_t)row * BSTR + c0 * 16;
        const uint32_t dl = dh + 128 * BSTR;
#pragma unroll
        for (int c = 0; c < 4; c++) {
            CP16(dh + c * 16, qh + c * 8);
            CP16(dl + c * 16, ql + c * 8);
        }
        CP_COMMIT();
    }
    CP_WAIT0();
    __syncthreads();

    uint32_t Qh[4][4], Ql[4][4];
    {
        const uint32_t qlane = (uint32_t)(wid * 16 + (lane & 15)) * BSTR +
                               (uint32_t)(lane >> 4) * 16;
#pragma unroll
        for (int ks = 0; ks < 4; ks++) {
            LDSM_X4(Qh[ks], sb + qlane + ks * 32);
            LDSM_X4(Ql[ks], sb + 128 * BSTR + qlane + ks * 32);
        }
    }
    __syncthreads();

    const int krow = tid >> 2;
    const int kc0  = (tid & 3) * 2;
    const __half* sKh = g_Kh + hbase + (size_t)krow * DK + kc0 * 8;
    const __half* sVh = g_Vh + hbase + (size_t)krow * DK + kc0 * 8;
    const uint32_t kdst = (uint32_t)krow * BSTR + kc0 * 16;

    auto prefetchKV = [&](int kb, int st) {
        const uint32_t s0 = sb + st * KV_STAGE + kdst;
        const size_t ko = (size_t)kb * 64 * DK;
        CP16(s0 + 0 * KV_TILE,      sKh + ko);
        CP16(s0 + 0 * KV_TILE + 16, sKh + ko + 8);
        CP16(s0 + 1 * KV_TILE,      sVh + ko);
        CP16(s0 + 1 * KV_TILE + 16, sVh + ko + 8);
    };

    const uint32_t k_lane = (uint32_t)((((lane >> 4) & 1) * 8 + (lane & 7))) * BSTR +
                            (uint32_t)((lane >> 3) & 1) * 16;
    const uint32_t v_lane = (uint32_t)((((lane >> 3) & 1) * 8 + (lane & 7))) * BSTR +
                            (uint32_t)((lane >> 4) & 1) * 16;

    float o[8][4];
#pragma unroll
    for (int nt = 0; nt < 8; nt++)
#pragma unroll
        for (int e = 0; e < 4; e++) o[nt][e] = 0.f;
    float m0 = -1e30f, m1 = -1e30f, l0 = 0.f, l1 = 0.f;

    const int row0 = qb * 128 + wid * 16 + g;
    const int kb_end = 2 * qb + 1;

    prefetchKV(0, 0);
    CP_COMMIT();

    for (int kb = 0; kb <= kb_end; kb++) {
        CP_WAIT0();
        __syncthreads();
        if (kb < kb_end) {
            prefetchKV(kb + 1, (kb + 1) & 1);
            CP_COMMIT();
        }
        const uint32_t st = sb + (kb & 1) * KV_STAGE;

        // ---- S = Q K^T (Q pre-scaled by 1/8; 2-product) ----
        float s[8][4];
#pragma unroll
        for (int nt = 0; nt < 8; nt++)
#pragma unroll
            for (int e = 0; e < 4; e++) s[nt][e] = 0.f;

#pragma unroll
        for (int ks = 0; ks < 4; ks++) {
#pragma unroll
            for (int np = 0; np < 4; np++) {
                const uint32_t ka = (uint32_t)(np * 16) * BSTR + ks * 32 + k_lane;
                uint32_t KB[4];
                LDSM_X4(KB, st + ka);
                mma_f16(s[2*np],   Qh[ks], KB[0], KB[1]);
                mma_f16(s[2*np+1], Qh[ks], KB[2], KB[3]);
                mma_f16(s[2*np],   Ql[ks], KB[0], KB[1]);
                mma_f16(s[2*np+1], Ql[ks], KB[2], KB[3]);
            }
        }

        if (kb >= 2 * qb) {
            const int cb = kb * 64 + 2 * tq;
#pragma unroll
            for (int nt = 0; nt < 8; nt++) {
                const int c = cb + nt * 8;
                if (c     > row0)     s[nt][0] = -1e9f;
                if (c + 1 > row0)     s[nt][1] = -1e9f;
                if (c     > row0 + 8) s[nt][2] = -1e9f;
                if (c + 1 > row0 + 8) s[nt][3] = -1e9f;
            }
        }

        float rm0 = -1e30f, rm1 = -1e30f;
#pragma unroll
        for (int nt = 0; nt < 8; nt++) {
            rm0 = fmaxf(rm0, fmaxf(s[nt][0], s[nt][1]));
            rm1 = fmaxf(rm1, fmaxf(s[nt][2], s[nt][3]));
        }
        rm0 = fmaxf(rm0, __shfl_xor_sync(0xffffffffu, rm0, 1));
        rm0 = fmaxf(rm0, __shfl_xor_sync(0xffffffffu, rm0, 2));
        rm1 = fmaxf(rm1, __shfl_xor_sync(0xffffffffu, rm1, 1));
        rm1 = fmaxf(rm1, __shfl_xor_sync(0xffffffffu, rm1, 2));

        const float nm0 = fmaxf(m0, rm0);
        const float nm1 = fmaxf(m1, rm1);
        const float c0 = __expf(m0 - nm0);
        const float c1 = __expf(m1 - nm1);
        m0 = nm0; m1 = nm1;

        float rs0 = 0.f, rs1 = 0.f;
#pragma unroll
        for (int nt = 0; nt < 8; nt++) {
            s[nt][0] = __expf(s[nt][0] - nm0); rs0 += s[nt][0];
            s[nt][1] = __expf(s[nt][1] - nm0); rs0 += s[nt][1];
            s[nt][2] = __expf(s[nt][2] - nm1); rs1 += s[nt][2];
            s[nt][3] = __expf(s[nt][3] - nm1); rs1 += s[nt][3];
        }
        rs0 += __shfl_xor_sync(0xffffffffu, rs0, 1);
        rs0 += __shfl_xor_sync(0xffffffffu, rs0, 2);
        rs1 += __shfl_xor_sync(0xffffffffu, rs1, 1);
        rs1 += __shfl_xor_sync(0xffffffffu, rs1, 2);
        l0 = l0 * c0 + rs0;
        l1 = l1 * c1 + rs1;

#pragma unroll
        for (int nt = 0; nt < 8; nt++) {
            o[nt][0] *= c0; o[nt][1] *= c0;
            o[nt][2] *= c1; o[nt][3] *= c1;
        }

        // ---- O += P V : P rounded once (1-product) ----
#pragma unroll
        for (int kt = 0; kt < 4; kt++) {
            uint32_t PA[4];
            __half2 p0 = __floats2half2_rn(s[2*kt][0],   s[2*kt][1]);
            __half2 p1 = __floats2half2_rn(s[2*kt][2],   s[2*kt][3]);
            __half2 p2 = __floats2half2_rn(s[2*kt+1][0], s[2*kt+1][1]);
            __half2 p3 = __floats2half2_rn(s[2*kt+1][2], s[2*kt+1][3]);
            PA[0] = *(uint32_t*)&p0; PA[1] = *(uint32_t*)&p1;
            PA[2] = *(uint32_t*)&p2; PA[3] = *(uint32_t*)&p3;
#pragma unroll
            for (int dp = 0; dp < 4; dp++) {
                const uint32_t va = (uint32_t)(kt * 16) * BSTR + dp * 32 + v_lane;
                uint32_t VB[4];
                LDSM_X4_T(VB, st + KV_TILE + va);
                mma_f16(o[2*dp],   PA, VB[0], VB[1]);
                mma_f16(o[2*dp+1], PA, VB[2], VB[3]);
            }
        }
        __syncthreads();
    }

    // ---- normalize + single-rounded ctx store ----
    const int b = bh >> 4;
    const int h = bh & 15;
    const float i0 = 1.f / l0;
    const float i1 = 1.f / l1;
    const size_t off0 = ((size_t)(b * SEQ + row0))     * DMODEL + h * DK + tq * 2;
    const size_t off1 = ((size_t)(b * SEQ + row0 + 8)) * DMODEL + h * DK + tq * 2;
#pragma unroll
    for (int nt = 0; nt < 8; nt++) {
        __half2 c0h = __floats2half2_rn(o[nt][0] * i0, o[nt][1] * i0);
        __half2 c1h = __floats2half2_rn(o[nt][2] * i1, o[nt][3] * i1);
        *(uint32_t*)&g_CtxH[off0 + nt * 8] = *(uint32_t*)&c0h;
        *(uint32_t*)&g_CtxH[off1 + nt * 8] = *(uint32_t*)&c1h;
    }
}

// ---------------------------------------------------------------------------
extern "C" void kernel_launch(void* const* d_in, const int* in_sizes, int n_in,
                              void* d_out, int out_size) {
    const float* q  = (const float*)d_in[0];
    const float* k  = (const float*)d_in[1];
    const float* v  = (const float*)d_in[2];
    const float* wq = (const float*)d_in[3];
    const float* wk = (const float*)d_in[4];
    const float* wv = (const float*)d_in[5];
    const float* wo = (const float*)d_in[6];
    float* out = (float*)d_out;

    static int configured = 0;
    if (!configured) {
        cudaFuncSetAttribute(gemm_hmma<0>, cudaFuncAttributeMaxDynamicSharedMemorySize, GEMM_SMEM);
        cudaFuncSetAttribute(gemm_hmma<1>, cudaFuncAttributeMaxDynamicSharedMemorySize, GEMM_SMEM);
        cudaFuncSetAttribute(gemm_hmma<2>, cudaFuncAttributeMaxDynamicSharedMemorySize, GEMM_SMEM);
        cudaFuncSetAttribute(attn_hmma, cudaFuncAttributeMaxDynamicSharedMemorySize, ATTN_SMEM);
        configured = 1;
    }

    dim3 gs(MROWS * DMODEL / (256 * 8), 7);    // (4096, 7)
    ksplit<<<gs, 256>>>(q, k, v, wq, wk, wv, wo);

    dim3 gq(DMODEL / 128, MROWS / 128);        // Q projection (2-product)
    gemm_hmma<0><<<gq, 512, GEMM_SMEM>>>(nullptr);

    dim3 gkv(DMODEL / 128, MROWS / 128, 2);    // K,V projections (1-product)
    gemm_hmma<2><<<gkv, 512, GEMM_SMEM>>>(nullptr);

    dim3 ga(SEQ / 128, BATCH * NHEADS);        // (16, 64)
    attn_hmma<<<ga, 256, ATTN_SMEM>>>();

    dim3 go(DMODEL / 128, MROWS / 128);        // output projection (1-product)
    gemm_hmma<1><<<go, 512, GEMM_SMEM>>>(out);
}

// round 16
// speedup vs baseline: 2.9085x; 1.2720x over previous
#include <cuda_runtime.h>
#include <cuda_bf16.h>
#include <cuda_fp16.h>
#include <cstdint>

#define BATCH   4
#define SEQ     2048
#define DMODEL  1024
#define NHEADS  16
#define DK      64
#define MROWS   (BATCH * SEQ)                 // 8192
#define HEADELEMS (BATCH * NHEADS * SEQ * DK) // 8M

// ---------------- persistent scratch (all single-rounded fp16) -------------
__device__ __half g_INh[3 * MROWS * DMODEL];
__device__ __half g_W[4 * DMODEL * DMODEL];   // Wq pre-scaled by 0.125*log2e
__device__ __half g_CtxH[MROWS * DMODEL];
__device__ __half g_Qh[HEADELEMS];            // Q in log2-softmax domain
__device__ __half g_Kh[HEADELEMS];
__device__ __half g_Vh[HEADELEMS];

// ============================ helpers ======================================
__device__ __forceinline__ uint32_t smem_u32(const void* p) {
    uint32_t a;
    asm("{ .reg .u64 t; cvta.to.shared.u64 t, %1; cvt.u32.u64 %0, t; }"
        : "=r"(a) : "l"(p));
    return a;
}
#define LDSM_X4(r, addr) \
    asm volatile("ldmatrix.sync.aligned.m8n8.x4.shared.b16 {%0,%1,%2,%3}, [%4];" \
        : "=r"((r)[0]), "=r"((r)[1]), "=r"((r)[2]), "=r"((r)[3]) : "r"(addr))
#define LDSM_X4_T(r, addr) \
    asm volatile("ldmatrix.sync.aligned.m8n8.x4.trans.shared.b16 {%0,%1,%2,%3}, [%4];" \
        : "=r"((r)[0]), "=r"((r)[1]), "=r"((r)[2]), "=r"((r)[3]) : "r"(addr))
#define CP16(dst, src) \
    asm volatile("cp.async.cg.shared.global [%0], [%1], 16;" \
                 :: "r"(dst), "l"(src) : "memory")
#define CP_COMMIT() asm volatile("cp.async.commit_group;" ::: "memory")
#define CP_WAIT0()  asm volatile("cp.async.wait_group 0;" ::: "memory")
#define CP_WAIT1()  asm volatile("cp.async.wait_group 1;" ::: "memory")

__device__ __forceinline__ void mma_f16(float* c, const uint32_t* a,
                                        uint32_t b0, uint32_t b1) {
    asm volatile("mma.sync.aligned.m16n8k16.row.col.f32.f16.f16.f32 "
        "{%0,%1,%2,%3}, {%4,%5,%6,%7}, {%8,%9}, {%0,%1,%2,%3};"
        : "+f"(c[0]), "+f"(c[1]), "+f"(c[2]), "+f"(c[3])
        : "r"(a[0]), "r"(a[1]), "r"(a[2]), "r"(a[3]), "r"(b0), "r"(b1));
}

// ===========================================================================
// Pre-convert pass: y 0-2 inputs -> fp16; y 3-6 weights -> fp16
// (Wq scaled by 0.125*log2e so attention scores are in log2 domain).
// ===========================================================================
#define QSCALE 0.1803368867f   // 0.125 * log2(e)

__global__ void __launch_bounds__(256) ksplit(
    const float* __restrict__ q, const float* __restrict__ k,
    const float* __restrict__ v, const float* __restrict__ wq,
    const float* __restrict__ wk, const float* __restrict__ wv,
    const float* __restrict__ wo) {
    const int sel = blockIdx.y;
    const int i = (blockIdx.x * 256 + threadIdx.x) * 8;
    float scale = 1.f;
    const float* src;
    __half* dst;
    if (sel < 3) {
        src = (sel == 0) ? q : (sel == 1) ? k : v;
        dst = g_INh + (size_t)sel * MROWS * DMODEL;
    } else {
        const int w = sel - 3;
        if (i >= DMODEL * DMODEL) return;
        src = (w == 0) ? wq : (w == 1) ? wk : (w == 2) ? wv : wo;
        dst = g_W + (size_t)w * DMODEL * DMODEL;
        if (w == 0) scale = QSCALE;
    }
    const float4 a = *(const float4*)(src + i);
    const float4 b = *(const float4*)(src + i + 4);
    __half2 h0 = __floats2half2_rn(a.x * scale, a.y * scale);
    __half2 h1 = __floats2half2_rn(a.z * scale, a.w * scale);
    __half2 h2 = __floats2half2_rn(b.x * scale, b.y * scale);
    __half2 h3 = __floats2half2_rn(b.z * scale, b.w * scale);
    *(uint4*)(dst + i) = make_uint4(*(uint32_t*)&h0, *(uint32_t*)&h1,
                                    *(uint32_t*)&h2, *(uint32_t*)&h3);
}

// ===========================================================================
// fp16 1-product HMMA NT GEMM. MODE 0 = QKV proj (z selects; rounded store,
// head-split). MODE 1 = out proj (g_CtxH x Wo -> float out).
// 512 threads, warp tile 32x32, CTA 128x128, BK=32, 3-stage cp.async.
// ===========================================================================
#define GS_ROW   80
#define GS_TILE  10240
#define GS_STAGE (2 * GS_TILE)           // A, B
#define GS_NSTG  3
#define GEMM_SMEM (GS_NSTG * GS_STAGE)   // 61440

template <int MODE>
__global__ void __launch_bounds__(512, 2) gemm_hmma(float* __restrict__ Yout) {
    extern __shared__ char smem[];
    const uint32_t sb = smem_u32(smem);
    const int tid  = threadIdx.x;
    const int wid  = tid >> 5;
    const int lane = tid & 31;
    const int m0 = blockIdx.y * 128;
    const int n0 = blockIdx.x * 128;

    const __half *Ah, *Bw;
    int z = 0;
    if (MODE == 0) {
        z  = blockIdx.z;                         // 0 Q, 1 K, 2 V
        Ah = g_INh + (size_t)z * MROWS * DMODEL;
        Bw = g_W + (size_t)z * DMODEL * DMODEL;
    } else {
        Ah = g_CtxH;
        Bw = g_W + (size_t)3 * DMODEL * DMODEL;  // Wo
    }

    const int prow = tid >> 2;
    const int pc   = tid & 3;
    const __half* srcA = Ah + (size_t)(m0 + prow) * DMODEL + pc * 8;
    const __half* srcB = Bw + (size_t)(n0 + prow) * DMODEL + pc * 8;
    const uint32_t pdst = (uint32_t)prow * GS_ROW + pc * 16;

    auto prefetch = [&](int ks, int st) {
        const uint32_t s0 = sb + st * GS_STAGE + pdst;
        const int ko = ks * 32;
        CP16(s0 + 0 * GS_TILE, srcA + ko);
        CP16(s0 + 1 * GS_TILE, srcB + ko);
    };

    const int wm = (wid & 3) * 32;
    const int wn = (wid >> 2) * 32;
    const int aRow  = lane & 15;
    const int aColB = (lane >> 4) * 16;
    const int bRow  = ((lane >> 4) << 3) + (lane & 7);
    const int bColB = ((lane >> 3) & 1) * 16;
    const uint32_t aOff = (uint32_t)(wm + aRow) * GS_ROW + aColB;
    const uint32_t bOff = (uint32_t)(wn + bRow) * GS_ROW + bColB;

    float acc[2][4][4];
#pragma unroll
    for (int mt = 0; mt < 2; mt++)
#pragma unroll
        for (int nt = 0; nt < 4; nt++)
#pragma unroll
            for (int e = 0; e < 4; e++) acc[mt][nt][e] = 0.f;

    prefetch(0, 0); CP_COMMIT();
    prefetch(1, 1); CP_COMMIT();

    int stg = 0;
    for (int ks = 0; ks < 32; ks++) {
        CP_WAIT1();
        __syncthreads();
        if (ks + 2 < 32) {
            const int nst = (stg + 2 >= GS_NSTG) ? stg + 2 - GS_NSTG : stg + 2;
            prefetch(ks + 2, nst);
        }
        CP_COMMIT();

        const uint32_t st = sb + stg * GS_STAGE;
        const uint32_t aB = st + aOff;
        const uint32_t bB = st + GS_TILE + bOff;

#pragma unroll
        for (int k16 = 0; k16 < 2; k16++) {
            const uint32_t kb = k16 * 32;
            uint32_t Af[2][4], Bf[2][4];
#pragma unroll
            for (int mt = 0; mt < 2; mt++)
                LDSM_X4(Af[mt], aB + mt * (16 * GS_ROW) + kb);
#pragma unroll
            for (int p = 0; p < 2; p++)
                LDSM_X4(Bf[p], bB + p * (16 * GS_ROW) + kb);
#pragma unroll
            for (int mt = 0; mt < 2; mt++)
#pragma unroll
                for (int nt = 0; nt < 4; nt++) {
                    const int p = nt >> 1, q2 = (nt & 1) * 2;
                    mma_f16(acc[mt][nt], Af[mt], Bf[p][q2], Bf[p][q2 + 1]);
                }
        }
        stg = (stg + 1 >= GS_NSTG) ? 0 : stg + 1;
    }

    // ---- epilogue ----
    const int g  = lane >> 2;
    const int tq = lane & 3;
#pragma unroll
    for (int mt = 0; mt < 2; mt++) {
#pragma unroll
        for (int nt = 0; nt < 4; nt++) {
            const int mrow = m0 + wm + mt * 16 + g;
            const int ncol = n0 + wn + nt * 8 + tq * 2;
#pragma unroll
            for (int half = 0; half < 2; half++) {
                const int m = mrow + half * 8;
                const float v0 = acc[mt][nt][half * 2 + 0];
                const float v1 = acc[mt][nt][half * 2 + 1];
                if (MODE == 1) {
                    *(float2*)&Yout[(size_t)m * DMODEL + ncol] = make_float2(v0, v1);
                } else {
                    const int b  = m >> 11;
                    const int s  = m & (SEQ - 1);
                    const int h  = ncol >> 6;
                    const int dc = ncol & 63;
                    const size_t off = ((size_t)(b * NHEADS + h) * SEQ + s) * DK + dc;
                    __half2 hv = __floats2half2_rn(v0, v1);
                    __half* O = (z == 0) ? g_Qh : (z == 1) ? g_Kh : g_Vh;
                    *(uint32_t*)&O[off] = *(uint32_t*)&hv;
                }
            }
        }
    }
}

// ===========================================================================
// fp16 1-product causal flash attention, log2-domain softmax (exp2f).
// S = Q·K^T (Q carries 0.125*log2e), PV with P rounded once. 2 CTAs/SM.
// ===========================================================================
#define BSTR     144
#define KV_TILE  (64 * BSTR)      // 9216
#define KV_STAGE (2 * KV_TILE)    // 18432
#define ATTN_SMEM (2 * KV_STAGE)  // 36864

__global__ void __launch_bounds__(256, 2) attn_hmma() {
    extern __shared__ char smem[];
    const uint32_t sb = smem_u32(smem);

    const int tid  = threadIdx.x;
    const int wid  = tid >> 5;
    const int lane = tid & 31;
    const int g    = lane >> 2;
    const int tq   = lane & 3;
    const int qb   = gridDim.x - 1 - blockIdx.x;
    const int bh   = blockIdx.y;

    const size_t hbase = (size_t)bh * SEQ * DK;

    // ---- stage Q (hi only): 2 threads/row x 4 chunks ----
    {
        const int row = tid >> 1;
        const int c0  = (tid & 1) * 4;
        const __half* qh = g_Qh + hbase + (size_t)(qb * 128 + row) * DK + c0 * 8;
        const uint32_t dh = sb + (uint32_t)row * BSTR + c0 * 16;
#pragma unroll
        for (int c = 0; c < 4; c++)
            CP16(dh + c * 16, qh + c * 8);
        CP_COMMIT();
    }
    CP_WAIT0();
    __syncthreads();

    uint32_t Qf[4][4];
    {
        const uint32_t qlane = (uint32_t)(wid * 16 + (lane & 15)) * BSTR +
                               (uint32_t)(lane >> 4) * 16;
#pragma unroll
        for (int ks = 0; ks < 4; ks++)
            LDSM_X4(Qf[ks], sb + qlane + ks * 32);
    }
    __syncthreads();

    const int krow = tid >> 2;
    const int kc0  = (tid & 3) * 2;
    const __half* sKh = g_Kh + hbase + (size_t)krow * DK + kc0 * 8;
    const __half* sVh = g_Vh + hbase + (size_t)krow * DK + kc0 * 8;
    const uint32_t kdst = (uint32_t)krow * BSTR + kc0 * 16;

    auto prefetchKV = [&](int kb, int st) {
        const uint32_t s0 = sb + st * KV_STAGE + kdst;
        const size_t ko = (size_t)kb * 64 * DK;
        CP16(s0 + 0 * KV_TILE,      sKh + ko);
        CP16(s0 + 0 * KV_TILE + 16, sKh + ko + 8);
        CP16(s0 + 1 * KV_TILE,      sVh + ko);
        CP16(s0 + 1 * KV_TILE + 16, sVh + ko + 8);
    };

    const uint32_t k_lane = (uint32_t)((((lane >> 4) & 1) * 8 + (lane & 7))) * BSTR +
                            (uint32_t)((lane >> 3) & 1) * 16;
    const uint32_t v_lane = (uint32_t)((((lane >> 3) & 1) * 8 + (lane & 7))) * BSTR +
                            (uint32_t)((lane >> 4) & 1) * 16;

    float o[8][4];
#pragma unroll
    for (int nt = 0; nt < 8; nt++)
#pragma unroll
        for (int e = 0; e < 4; e++) o[nt][e] = 0.f;
    float m0 = -1e30f, m1 = -1e30f, l0 = 0.f, l1 = 0.f;

    const int row0 = qb * 128 + wid * 16 + g;
    const int kb_end = 2 * qb + 1;

    prefetchKV(0, 0);
    CP_COMMIT();

    for (int kb = 0; kb <= kb_end; kb++) {
        CP_WAIT0();
        __syncthreads();
        if (kb < kb_end) {
            prefetchKV(kb + 1, (kb + 1) & 1);
            CP_COMMIT();
        }
        const uint32_t st = sb + (kb & 1) * KV_STAGE;

        // ---- S = Q K^T (1-product; scores in log2 domain) ----
        float s[8][4];
#pragma unroll
        for (int nt = 0; nt < 8; nt++)
#pragma unroll
            for (int e = 0; e < 4; e++) s[nt][e] = 0.f;

#pragma unroll
        for (int ks = 0; ks < 4; ks++) {
#pragma unroll
            for (int np = 0; np < 4; np++) {
                const uint32_t ka = (uint32_t)(np * 16) * BSTR + ks * 32 + k_lane;
                uint32_t KB[4];
                LDSM_X4(KB, st + ka);
                mma_f16(s[2*np],   Qf[ks], KB[0], KB[1]);
                mma_f16(s[2*np+1], Qf[ks], KB[2], KB[3]);
            }
        }

        if (kb >= 2 * qb) {
            const int cb = kb * 64 + 2 * tq;
#pragma unroll
            for (int nt = 0; nt < 8; nt++) {
                const int c = cb + nt * 8;
                if (c     > row0)     s[nt][0] = -1e9f;
                if (c + 1 > row0)     s[nt][1] = -1e9f;
                if (c     > row0 + 8) s[nt][2] = -1e9f;
                if (c + 1 > row0 + 8) s[nt][3] = -1e9f;
            }
        }

        float rm0 = -1e30f, rm1 = -1e30f;
#pragma unroll
        for (int nt = 0; nt < 8; nt++) {
            rm0 = fmaxf(rm0, fmaxf(s[nt][0], s[nt][1]));
            rm1 = fmaxf(rm1, fmaxf(s[nt][2], s[nt][3]));
        }
        rm0 = fmaxf(rm0, __shfl_xor_sync(0xffffffffu, rm0, 1));
        rm0 = fmaxf(rm0, __shfl_xor_sync(0xffffffffu, rm0, 2));
        rm1 = fmaxf(rm1, __shfl_xor_sync(0xffffffffu, rm1, 1));
        rm1 = fmaxf(rm1, __shfl_xor_sync(0xffffffffu, rm1, 2));

        const float nm0 = fmaxf(m0, rm0);
        const float nm1 = fmaxf(m1, rm1);
        const float c0 = exp2f(m0 - nm0);
        const float c1 = exp2f(m1 - nm1);
        m0 = nm0; m1 = nm1;

        float rs0 = 0.f, rs1 = 0.f;
#pragma unroll
        for (int nt = 0; nt < 8; nt++) {
            s[nt][0] = exp2f(s[nt][0] - nm0); rs0 += s[nt][0];
            s[nt][1] = exp2f(s[nt][1] - nm0); rs0 += s[nt][1];
            s[nt][2] = exp2f(s[nt][2] - nm1); rs1 += s[nt][2];
            s[nt][3] = exp2f(s[nt][3] - nm1); rs1 += s[nt][3];
        }
        rs0 += __shfl_xor_sync(0xffffffffu, rs0, 1);
        rs0 += __shfl_xor_sync(0xffffffffu, rs0, 2);
        rs1 += __shfl_xor_sync(0xffffffffu, rs1, 1);
        rs1 += __shfl_xor_sync(0xffffffffu, rs1, 2);
        l0 = l0 * c0 + rs0;
        l1 = l1 * c1 + rs1;

#pragma unroll
        for (int nt = 0; nt < 8; nt++) {
            o[nt][0] *= c0; o[nt][1] *= c0;
            o[nt][2] *= c1; o[nt][3] *= c1;
        }

        // ---- O += P V (P rounded once) ----
#pragma unroll
        for (int kt = 0; kt < 4; kt++) {
            uint32_t PA[4];
            __half2 p0 = __floats2half2_rn(s[2*kt][0],   s[2*kt][1]);
            __half2 p1 = __floats2half2_rn(s[2*kt][2],   s[2*kt][3]);
            __half2 p2 = __floats2half2_rn(s[2*kt+1][0], s[2*kt+1][1]);
            __half2 p3 = __floats2half2_rn(s[2*kt+1][2], s[2*kt+1][3]);
            PA[0] = *(uint32_t*)&p0; PA[1] = *(uint32_t*)&p1;
            PA[2] = *(uint32_t*)&p2; PA[3] = *(uint32_t*)&p3;
#pragma unroll
            for (int dp = 0; dp < 4; dp++) {
                const uint32_t va = (uint32_t)(kt * 16) * BSTR + dp * 32 + v_lane;
                uint32_t VB[4];
                LDSM_X4_T(VB, st + KV_TILE + va);
                mma_f16(o[2*dp],   PA, VB[0], VB[1]);
                mma_f16(o[2*dp+1], PA, VB[2], VB[3]);
            }
        }
        __syncthreads();
    }

    // ---- normalize + single-rounded ctx store ----
    const int b = bh >> 4;
    const int h = bh & 15;
    const float i0 = 1.f / l0;
    const float i1 = 1.f / l1;
    const size_t off0 = ((size_t)(b * SEQ + row0))     * DMODEL + h * DK + tq * 2;
    const size_t off1 = ((size_t)(b * SEQ + row0 + 8)) * DMODEL + h * DK + tq * 2;
#pragma unroll
    for (int nt = 0; nt < 8; nt++) {
        __half2 c0h = __floats2half2_rn(o[nt][0] * i0, o[nt][1] * i0);
        __half2 c1h = __floats2half2_rn(o[nt][2] * i1, o[nt][3] * i1);
        *(uint32_t*)&g_CtxH[off0 + nt * 8] = *(uint32_t*)&c0h;
        *(uint32_t*)&g_CtxH[off1 + nt * 8] = *(uint32_t*)&c1h;
    }
}

// ---------------------------------------------------------------------------
extern "C" void kernel_launch(void* const* d_in, const int* in_sizes, int n_in,
                              void* d_out, int out_size) {
    const float* q  = (const float*)d_in[0];
    const float* k  = (const float*)d_in[1];
    const float* v  = (const float*)d_in[2];
    const float* wq = (const float*)d_in[3];
    const float* wk = (const float*)d_in[4];
    const float* wv = (const float*)d_in[5];
    const float* wo = (const float*)d_in[6];
    float* out = (float*)d_out;

    static int configured = 0;
    if (!configured) {
        cudaFuncSetAttribute(gemm_hmma<0>, cudaFuncAttributeMaxDynamicSharedMemorySize, GEMM_SMEM);
        cudaFuncSetAttribute(gemm_hmma<1>, cudaFuncAttributeMaxDynamicSharedMemorySize, GEMM_SMEM);
        cudaFuncSetAttribute(attn_hmma, cudaFuncAttributeMaxDynamicSharedMemorySize, ATTN_SMEM);
        configured = 1;
    }

    dim3 gs(MROWS * DMODEL / (256 * 8), 7);    // (4096, 7)
    ksplit<<<gs, 256>>>(q, k, v, wq, wk, wv, wo);

    dim3 gqkv(DMODEL / 128, MROWS / 128, 3);   // fused Q,K,V projections
    gemm_hmma<0><<<gqkv, 512, GEMM_SMEM>>>(nullptr);

    dim3 ga(SEQ / 128, BATCH * NHEADS);        // (16, 64)
    attn_hmma<<<ga, 256, ATTN_SMEM>>>();

    dim3 go(DMODEL / 128, MROWS / 128);        // output projection
    gemm_hmma<1><<<go, 512, GEMM_SMEM>>>(out);
}

// round 17
// speedup vs baseline: 2.9235x; 1.0051x over previous
#include <cuda_runtime.h>
#include <cuda_bf16.h>
#include <cuda_fp16.h>
#include <cstdint>

#define BATCH   4
#define SEQ     2048
#define DMODEL  1024
#define NHEADS  16
#define DK      64
#define MROWS   (BATCH * SEQ)                 // 8192
#define HEADELEMS (BATCH * NHEADS * SEQ * DK) // 8M

// ---------------- persistent scratch (all single-rounded fp16) -------------
__device__ __half g_INh[3 * MROWS * DMODEL];
__device__ __half g_W[4 * DMODEL * DMODEL];   // Wq pre-scaled by 0.125*log2e
__device__ __half g_CtxH[MROWS * DMODEL];
__device__ __half g_Qh[HEADELEMS];            // Q in log2-softmax domain
__device__ __half g_Kh[HEADELEMS];
__device__ __half g_Vh[HEADELEMS];

// ============================ helpers ======================================
__device__ __forceinline__ uint32_t smem_u32(const void* p) {
    uint32_t a;
    asm("{ .reg .u64 t; cvta.to.shared.u64 t, %1; cvt.u32.u64 %0, t; }"
        : "=r"(a) : "l"(p));
    return a;
}
#define LDSM_X4(r, addr) \
    asm volatile("ldmatrix.sync.aligned.m8n8.x4.shared.b16 {%0,%1,%2,%3}, [%4];" \
        : "=r"((r)[0]), "=r"((r)[1]), "=r"((r)[2]), "=r"((r)[3]) : "r"(addr))
#define LDSM_X4_T(r, addr) \
    asm volatile("ldmatrix.sync.aligned.m8n8.x4.trans.shared.b16 {%0,%1,%2,%3}, [%4];" \
        : "=r"((r)[0]), "=r"((r)[1]), "=r"((r)[2]), "=r"((r)[3]) : "r"(addr))
#define CP16(dst, src) \
    asm volatile("cp.async.cg.shared.global [%0], [%1], 16;" \
                 :: "r"(dst), "l"(src) : "memory")
#define CP_COMMIT() asm volatile("cp.async.commit_group;" ::: "memory")
#define CP_WAIT0()  asm volatile("cp.async.wait_group 0;" ::: "memory")
#define CP_WAIT1()  asm volatile("cp.async.wait_group 1;" ::: "memory")

__device__ __forceinline__ void mma_f16(float* c, const uint32_t* a,
                                        uint32_t b0, uint32_t b1) {
    asm volatile("mma.sync.aligned.m16n8k16.row.col.f32.f16.f16.f32 "
        "{%0,%1,%2,%3}, {%4,%5,%6,%7}, {%8,%9}, {%0,%1,%2,%3};"
        : "+f"(c[0]), "+f"(c[1]), "+f"(c[2]), "+f"(c[3])
        : "r"(a[0]), "r"(a[1]), "r"(a[2]), "r"(a[3]), "r"(b0), "r"(b1));
}
__device__ __forceinline__ float ex2(float x) {
    float r;
    asm("ex2.approx.f32 %0, %1;" : "=f"(r) : "f"(x));
    return r;
}

// ===========================================================================
// Pre-convert pass: y 0-2 inputs -> fp16; y 3-6 weights -> fp16
// (Wq scaled by 0.125*log2e so attention scores are in log2 domain).
// ===========================================================================
#define QSCALE 0.1803368867f   // 0.125 * log2(e)

__global__ void __launch_bounds__(256) ksplit(
    const float* __restrict__ q, const float* __restrict__ k,
    const float* __restrict__ v, const float* __restrict__ wq,
    const float* __restrict__ wk, const float* __restrict__ wv,
    const float* __restrict__ wo) {
    const int sel = blockIdx.y;
    const int i = (blockIdx.x * 256 + threadIdx.x) * 8;
    float scale = 1.f;
    const float* src;
    __half* dst;
    if (sel < 3) {
        src = (sel == 0) ? q : (sel == 1) ? k : v;
        dst = g_INh + (size_t)sel * MROWS * DMODEL;
    } else {
        const int w = sel - 3;
        if (i >= DMODEL * DMODEL) return;
        src = (w == 0) ? wq : (w == 1) ? wk : (w == 2) ? wv : wo;
        dst = g_W + (size_t)w * DMODEL * DMODEL;
        if (w == 0) scale = QSCALE;
    }
    const float4 a = *(const float4*)(src + i);
    const float4 b = *(const float4*)(src + i + 4);
    __half2 h0 = __floats2half2_rn(a.x * scale, a.y * scale);
    __half2 h1 = __floats2half2_rn(a.z * scale, a.w * scale);
    __half2 h2 = __floats2half2_rn(b.x * scale, b.y * scale);
    __half2 h3 = __floats2half2_rn(b.z * scale, b.w * scale);
    *(uint4*)(dst + i) = make_uint4(*(uint32_t*)&h0, *(uint32_t*)&h1,
                                    *(uint32_t*)&h2, *(uint32_t*)&h3);
}

// ===========================================================================
// fp16 1-product HMMA NT GEMM (unchanged from round 16).
// ===========================================================================
#define GS_ROW   80
#define GS_TILE  10240
#define GS_STAGE (2 * GS_TILE)           // A, B
#define GS_NSTG  3
#define GEMM_SMEM (GS_NSTG * GS_STAGE)   // 61440

template <int MODE>
__global__ void __launch_bounds__(512, 2) gemm_hmma(float* __restrict__ Yout) {
    extern __shared__ char smem[];
    const uint32_t sb = smem_u32(smem);
    const int tid  = threadIdx.x;
    const int wid  = tid >> 5;
    const int lane = tid & 31;
    const int m0 = blockIdx.y * 128;
    const int n0 = blockIdx.x * 128;

    const __half *Ah, *Bw;
    int z = 0;
    if (MODE == 0) {
        z  = blockIdx.z;                         // 0 Q, 1 K, 2 V
        Ah = g_INh + (size_t)z * MROWS * DMODEL;
        Bw = g_W + (size_t)z * DMODEL * DMODEL;
    } else {
        Ah = g_CtxH;
        Bw = g_W + (size_t)3 * DMODEL * DMODEL;  // Wo
    }

    const int prow = tid >> 2;
    const int pc   = tid & 3;
    const __half* srcA = Ah + (size_t)(m0 + prow) * DMODEL + pc * 8;
    const __half* srcB = Bw + (size_t)(n0 + prow) * DMODEL + pc * 8;
    const uint32_t pdst = (uint32_t)prow * GS_ROW + pc * 16;

    auto prefetch = [&](int ks, int st) {
        const uint32_t s0 = sb + st * GS_STAGE + pdst;
        const int ko = ks * 32;
        CP16(s0 + 0 * GS_TILE, srcA + ko);
        CP16(s0 + 1 * GS_TILE, srcB + ko);
    };

    const int wm = (wid & 3) * 32;
    const int wn = (wid >> 2) * 32;
    const int aRow  = lane & 15;
    const int aColB = (lane >> 4) * 16;
    const int bRow  = ((lane >> 4) << 3) + (lane & 7);
    const int bColB = ((lane >> 3) & 1) * 16;
    const uint32_t aOff = (uint32_t)(wm + aRow) * GS_ROW + aColB;
    const uint32_t bOff = (uint32_t)(wn + bRow) * GS_ROW + bColB;

    float acc[2][4][4];
#pragma unroll
    for (int mt = 0; mt < 2; mt++)
#pragma unroll
        for (int nt = 0; nt < 4; nt++)
#pragma unroll
            for (int e = 0; e < 4; e++) acc[mt][nt][e] = 0.f;

    prefetch(0, 0); CP_COMMIT();
    prefetch(1, 1); CP_COMMIT();

    int stg = 0;
    for (int ks = 0; ks < 32; ks++) {
        CP_WAIT1();
        __syncthreads();
        if (ks + 2 < 32) {
            const int nst = (stg + 2 >= GS_NSTG) ? stg + 2 - GS_NSTG : stg + 2;
            prefetch(ks + 2, nst);
        }
        CP_COMMIT();

        const uint32_t st = sb + stg * GS_STAGE;
        const uint32_t aB = st + aOff;
        const uint32_t bB = st + GS_TILE + bOff;

#pragma unroll
        for (int k16 = 0; k16 < 2; k16++) {
            const uint32_t kb = k16 * 32;
            uint32_t Af[2][4], Bf[2][4];
#pragma unroll
            for (int mt = 0; mt < 2; mt++)
                LDSM_X4(Af[mt], aB + mt * (16 * GS_ROW) + kb);
#pragma unroll
            for (int p = 0; p < 2; p++)
                LDSM_X4(Bf[p], bB + p * (16 * GS_ROW) + kb);
#pragma unroll
            for (int mt = 0; mt < 2; mt++)
#pragma unroll
                for (int nt = 0; nt < 4; nt++) {
                    const int p = nt >> 1, q2 = (nt & 1) * 2;
                    mma_f16(acc[mt][nt], Af[mt], Bf[p][q2], Bf[p][q2 + 1]);
                }
        }
        stg = (stg + 1 >= GS_NSTG) ? 0 : stg + 1;
    }

    // ---- epilogue ----
    const int g  = lane >> 2;
    const int tq = lane & 3;
#pragma unroll
    for (int mt = 0; mt < 2; mt++) {
#pragma unroll
        for (int nt = 0; nt < 4; nt++) {
            const int mrow = m0 + wm + mt * 16 + g;
            const int ncol = n0 + wn + nt * 8 + tq * 2;
#pragma unroll
            for (int half = 0; half < 2; half++) {
                const int m = mrow + half * 8;
                const float v0 = acc[mt][nt][half * 2 + 0];
                const float v1 = acc[mt][nt][half * 2 + 1];
                if (MODE == 1) {
                    *(float2*)&Yout[(size_t)m * DMODEL + ncol] = make_float2(v0, v1);
                } else {
                    const int b  = m >> 11;
                    const int s  = m & (SEQ - 1);
                    const int h  = ncol >> 6;
                    const int dc = ncol & 63;
                    const size_t off = ((size_t)(b * NHEADS + h) * SEQ + s) * DK + dc;
                    __half2 hv = __floats2half2_rn(v0, v1);
                    __half* O = (z == 0) ? g_Qh : (z == 1) ? g_Kh : g_Vh;
                    *(uint32_t*)&O[off] = *(uint32_t*)&hv;
                }
            }
        }
    }
}

// ===========================================================================
// fp16 1-product causal flash attention, log2-domain softmax (ex2.approx).
// 3-stage KV pipeline (wait_group 1), single barrier per iteration.
// Q staged concurrently with KV(0)/KV(1) in the stage-2 area. 2 CTAs/SM.
// ===========================================================================
#define BSTR     144
#define KV_TILE  (64 * BSTR)      // 9216
#define KV_STAGE (2 * KV_TILE)    // 18432
#define KV_NSTG  3
#define ATTN_SMEM (KV_NSTG * KV_STAGE)  // 55296

__global__ void __launch_bounds__(256, 2) attn_hmma() {
    extern __shared__ char smem[];
    const uint32_t sb = smem_u32(smem);

    const int tid  = threadIdx.x;
    const int wid  = tid >> 5;
    const int lane = tid & 31;
    const int g    = lane >> 2;
    const int tq   = lane & 3;
    const int qb   = gridDim.x - 1 - blockIdx.x;   // heavy blocks first
    const int bh   = blockIdx.y;

    const size_t hbase = (size_t)bh * SEQ * DK;
    const int kb_end = 2 * qb + 1;                 // >= 1 always

    // KV prefetch mapping: 64 rows x 8 chunks; 4 threads/row x 2 chunks each
    const int krow = tid >> 2;
    const int kc0  = (tid & 3) * 2;
    const __half* sKh = g_Kh + hbase + (size_t)krow * DK + kc0 * 8;
    const __half* sVh = g_Vh + hbase + (size_t)krow * DK + kc0 * 8;
    const uint32_t kdst = (uint32_t)krow * BSTR + kc0 * 16;

    auto prefetchKV = [&](int kb, int st) {
        const uint32_t s0 = sb + st * KV_STAGE + kdst;
        const size_t ko = (size_t)kb * 64 * DK;
        CP16(s0 + 0 * KV_TILE,      sKh + ko);
        CP16(s0 + 0 * KV_TILE + 16, sKh + ko + 8);
        CP16(s0 + 1 * KV_TILE,      sVh + ko);
        CP16(s0 + 1 * KV_TILE + 16, sVh + ko + 8);
    };

    // ---- prologue: KV(0)->st0, KV(1)->st1, Q->st2 area, all overlapped ----
    prefetchKV(0, 0); CP_COMMIT();
    prefetchKV(1, 1); CP_COMMIT();
    {
        const int row = tid >> 1;
        const int c0  = (tid & 1) * 4;
        const __half* qh = g_Qh + hbase + (size_t)(qb * 128 + row) * DK + c0 * 8;
        const uint32_t dh = sb + 2 * KV_STAGE + (uint32_t)row * BSTR + c0 * 16;
#pragma unroll
        for (int c = 0; c < 4; c++)
            CP16(dh + c * 16, qh + c * 8);
        CP_COMMIT();
    }
    CP_WAIT0();
    __syncthreads();

    uint32_t Qf[4][4];
    {
        const uint32_t qlane = sb + 2 * KV_STAGE +
                               (uint32_t)(wid * 16 + (lane & 15)) * BSTR +
                               (uint32_t)(lane >> 4) * 16;
#pragma unroll
        for (int ks = 0; ks < 4; ks++)
            LDSM_X4(Qf[ks], qlane + ks * 32);
    }
    __syncthreads();   // Q reads done before kb=0 prefetches into st2

    const uint32_t k_lane = (uint32_t)((((lane >> 4) & 1) * 8 + (lane & 7))) * BSTR +
                            (uint32_t)((lane >> 3) & 1) * 16;
    const uint32_t v_lane = (uint32_t)((((lane >> 3) & 1) * 8 + (lane & 7))) * BSTR +
                            (uint32_t)((lane >> 4) & 1) * 16;

    float o[8][4];
#pragma unroll
    for (int nt = 0; nt < 8; nt++)
#pragma unroll
        for (int e = 0; e < 4; e++) o[nt][e] = 0.f;
    float m0 = -1e30f, m1 = -1e30f, l0 = 0.f, l1 = 0.f;

    const int row0 = qb * 128 + wid * 16 + g;

    int stg = 0;
    for (int kb = 0; kb <= kb_end; kb++) {
        if (kb) {
            CP_WAIT1();
            __syncthreads();
        }
        if (kb + 2 <= kb_end) {
            const int nst = (stg + 2 >= KV_NSTG) ? stg + 2 - KV_NSTG : stg + 2;
            prefetchKV(kb + 2, nst);
        }
        CP_COMMIT();
        const uint32_t st = sb + stg * KV_STAGE;

        // ---- S = Q K^T (1-product; scores in log2 domain) ----
        float s[8][4];
#pragma unroll
        for (int nt = 0; nt < 8; nt++)
#pragma unroll
            for (int e = 0; e < 4; e++) s[nt][e] = 0.f;

#pragma unroll
        for (int ks = 0; ks < 4; ks++) {
#pragma unroll
            for (int np = 0; np < 4; np++) {
                const uint32_t ka = (uint32_t)(np * 16) * BSTR + ks * 32 + k_lane;
                uint32_t KB[4];
                LDSM_X4(KB, st + ka);
                mma_f16(s[2*np],   Qf[ks], KB[0], KB[1]);
                mma_f16(s[2*np+1], Qf[ks], KB[2], KB[3]);
            }
        }

        if (kb >= 2 * qb) {
            const int cb = kb * 64 + 2 * tq;
#pragma unroll
            for (int nt = 0; nt < 8; nt++) {
                const int c = cb + nt * 8;
                if (c     > row0)     s[nt][0] = -1e9f;
                if (c + 1 > row0)     s[nt][1] = -1e9f;
                if (c     > row0 + 8) s[nt][2] = -1e9f;
                if (c + 1 > row0 + 8) s[nt][3] = -1e9f;
            }
        }

        float rm0 = -1e30f, rm1 = -1e30f;
#pragma unroll
        for (int nt = 0; nt < 8; nt++) {
            rm0 = fmaxf(rm0, fmaxf(s[nt][0], s[nt][1]));
            rm1 = fmaxf(rm1, fmaxf(s[nt][2], s[nt][3]));
        }
        rm0 = fmaxf(rm0, __shfl_xor_sync(0xffffffffu, rm0, 1));
        rm0 = fmaxf(rm0, __shfl_xor_sync(0xffffffffu, rm0, 2));
        rm1 = fmaxf(rm1, __shfl_xor_sync(0xffffffffu, rm1, 1));
        rm1 = fmaxf(rm1, __shfl_xor_sync(0xffffffffu, rm1, 2));

        const float nm0 = fmaxf(m0, rm0);
        const float nm1 = fmaxf(m1, rm1);
        const float c0 = ex2(m0 - nm0);
        const float c1 = ex2(m1 - nm1);
        m0 = nm0; m1 = nm1;

        float rs0 = 0.f, rs1 = 0.f;
#pragma unroll
        for (int nt = 0; nt < 8; nt++) {
            s[nt][0] = ex2(s[nt][0] - nm0); rs0 += s[nt][0];
            s[nt][1] = ex2(s[nt][1] - nm0); rs0 += s[nt][1];
            s[nt][2] = ex2(s[nt][2] - nm1); rs1 += s[nt][2];
            s[nt][3] = ex2(s[nt][3] - nm1); rs1 += s[nt][3];
        }
        rs0 += __shfl_xor_sync(0xffffffffu, rs0, 1);
        rs0 += __shfl_xor_sync(0xffffffffu, rs0, 2);
        rs1 += __shfl_xor_sync(0xffffffffu, rs1, 1);
        rs1 += __shfl_xor_sync(0xffffffffu, rs1, 2);
        l0 = l0 * c0 + rs0;
        l1 = l1 * c1 + rs1;

#pragma unroll
        for (int nt = 0; nt < 8; nt++) {
            o[nt][0] *= c0; o[nt][1] *= c0;
            o[nt][2] *= c1; o[nt][3] *= c1;
        }

        // ---- O += P V (P rounded once) ----
#pragma unroll
        for (int kt = 0; kt < 4; kt++) {
            uint32_t PA[4];
            __half2 p0 = __floats2half2_rn(s[2*kt][0],   s[2*kt][1]);
            __half2 p1 = __floats2half2_rn(s[2*kt][2],   s[2*kt][3]);
            __half2 p2 = __floats2half2_rn(s[2*kt+1][0], s[2*kt+1][1]);
            __half2 p3 = __floats2half2_rn(s[2*kt+1][2], s[2*kt+1][3]);
            PA[0] = *(uint32_t*)&p0; PA[1] = *(uint32_t*)&p1;
            PA[2] = *(uint32_t*)&p2; PA[3] = *(uint32_t*)&p3;
#pragma unroll
            for (int dp = 0; dp < 4; dp++) {
                const uint32_t va = (uint32_t)(kt * 16) * BSTR + dp * 32 + v_lane;
                uint32_t VB[4];
                LDSM_X4_T(VB, st + KV_TILE + va);
                mma_f16(o[2*dp],   PA, VB[0], VB[1]);
                mma_f16(o[2*dp+1], PA, VB[2], VB[3]);
            }
        }
        stg = (stg + 1 >= KV_NSTG) ? 0 : stg + 1;
    }

    // ---- normalize + single-rounded ctx store ----
    const int b = bh >> 4;
    const int h = bh & 15;
    const float i0 = 1.f / l0;
    const float i1 = 1.f / l1;
    const size_t off0 = ((size_t)(b * SEQ + row0))     * DMODEL + h * DK + tq * 2;
    const size_t off1 = ((size_t)(b * SEQ + row0 + 8)) * DMODEL + h * DK + tq * 2;
#pragma unroll
    for (int nt = 0; nt < 8; nt++) {
        __half2 c0h = __floats2half2_rn(o[nt][0] * i0, o[nt][1] * i0);
        __half2 c1h = __floats2half2_rn(o[nt][2] * i1, o[nt][3] * i1);
        *(uint32_t*)&g_CtxH[off0 + nt * 8] = *(uint32_t*)&c0h;
        *(uint32_t*)&g_CtxH[off1 + nt * 8] = *(uint32_t*)&c1h;
    }
}

// ---------------------------------------------------------------------------
extern "C" void kernel_launch(void* const* d_in, const int* in_sizes, int n_in,
                              void* d_out, int out_size) {
    const float* q  = (const float*)d_in[0];
    const float* k  = (const float*)d_in[1];
    const float* v  = (const float*)d_in[2];
    const float* wq = (const float*)d_in[3];
    const float* wk = (const float*)d_in[4];
    const float* wv = (const float*)d_in[5];
    const float* wo = (const float*)d_in[6];
    float* out = (float*)d_out;

    static int configured = 0;
    if (!configured) {
        cudaFuncSetAttribute(gemm_hmma<0>, cudaFuncAttributeMaxDynamicSharedMemorySize, GEMM_SMEM);
        cudaFuncSetAttribute(gemm_hmma<1>, cudaFuncAttributeMaxDynamicSharedMemorySize, GEMM_SMEM);
        cudaFuncSetAttribute(attn_hmma, cudaFuncAttributeMaxDynamicSharedMemorySize, ATTN_SMEM);
        configured = 1;
    }

    dim3 gs(MROWS * DMODEL / (256 * 8), 7);    // (4096, 7)
    ksplit<<<gs, 256>>>(q, k, v, wq, wk, wv, wo);

    dim3 gqkv(DMODEL / 128, MROWS / 128, 3);   // fused Q,K,V projections
    gemm_hmma<0><<<gqkv, 512, GEMM_SMEM>>>(nullptr);

    dim3 ga(SEQ / 128, BATCH * NHEADS);        // (16, 64)
    attn_hmma<<<ga, 256, ATTN_SMEM>>>();

    dim3 go(DMODEL / 128, MROWS / 128);        // output projection
    gemm_hmma<1><<<go, 512, GEMM_SMEM>>>(out);
}